// round 12
// baseline (speedup 1.0000x reference)
#include <cuda_runtime.h>
#include <math.h>

// Problem constants
#define LSEQ 8192
#define NFFT 16384          // 2*LSEQ = 32*32*16
#define DM   768
#define EMB  33
#define FO   64
#define SHIFT_C 0.05f
#define NT   512            // FFT threads per CTA

// Pad 1 float2 per 16: PHYS(i) = i + (i>>4).  (verified conflict-free R5)
#define DPAD 17408
#define SMEM_BYTES (DPAD * (int)sizeof(float2))          // 139264 B

// ---------------- scratch (device globals: no allocations allowed) ----------
__device__ float g_S[LSEQ * FO];                         // post-MLP activations
__device__ float g_k[DM * LSEQ];                         // filter k[d][l]
__device__ __align__(16) float2 g_Kf[(size_t)DM * NFFT]; // (spectrum + D)/N, scrambled

// cos / (-sin) of 2*pi*k/32 as compile-time constants -> immediate-form FFMA
__device__ static constexpr float CS32[32] = {
    1.0f,                   0.98078528040323044f,  0.92387953251128674f,  0.83146961230254524f,
    0.70710678118654752f,   0.55557023301960222f,  0.38268343236508977f,  0.19509032201612827f,
    0.0f,                  -0.19509032201612827f, -0.38268343236508977f, -0.55557023301960222f,
   -0.70710678118654752f,  -0.83146961230254524f, -0.92387953251128674f, -0.98078528040323044f,
   -1.0f,                  -0.98078528040323044f, -0.92387953251128674f, -0.83146961230254524f,
   -0.70710678118654752f,  -0.55557023301960222f, -0.38268343236508977f, -0.19509032201612827f,
    0.0f,                   0.19509032201612827f,  0.38268343236508977f,  0.55557023301960222f,
    0.70710678118654752f,   0.83146961230254524f,  0.92387953251128674f,  0.98078528040323044f
};
__device__ static constexpr float SN32[32] = {     // = sin(-2*pi*k/32)
    0.0f,                  -0.19509032201612827f, -0.38268343236508977f, -0.55557023301960222f,
   -0.70710678118654752f,  -0.83146961230254524f, -0.92387953251128674f, -0.98078528040323044f,
   -1.0f,                  -0.98078528040323044f, -0.92387953251128674f, -0.83146961230254524f,
   -0.70710678118654752f,  -0.55557023301960222f, -0.38268343236508977f, -0.19509032201612827f,
    0.0f,                   0.19509032201612827f,  0.38268343236508977f,  0.55557023301960222f,
    0.70710678118654752f,   0.83146961230254524f,  0.92387953251128674f,  0.98078528040323044f,
    1.0f,                   0.98078528040323044f,  0.92387953251128674f,  0.83146961230254524f,
    0.70710678118654752f,   0.55557023301960222f,  0.38268343236508977f,  0.19509032201612827f
};

// ---------------- complex helpers ----------------
__device__ __forceinline__ float2 cadd(float2 a, float2 b){ return make_float2(a.x+b.x, a.y+b.y); }
__device__ __forceinline__ float2 csub(float2 a, float2 b){ return make_float2(a.x-b.x, a.y-b.y); }
__device__ __forceinline__ float2 cmul(float2 a, float2 b){
    return make_float2(a.x*b.x - a.y*b.y, a.x*b.y + a.y*b.x);
}
// multiply by compile-time literal (wx, wy): 2 FMUL-imm + 2 FFMA-imm (rt=1)
__device__ __forceinline__ float2 cmuli(float2 a, float wx, float wy) {
    return make_float2(fmaf(a.y, -wy, a.x * wx), fmaf(a.y, wx, a.x * wy));
}
// a * e^{-2*pi*i*k/32}; k folded to constant under #pragma unroll
__device__ __forceinline__ float2 twf(float2 a, int k) {
    k &= 31;
    if (k == 0)  return a;
    if (k == 8)  return make_float2(a.y, -a.x);     // * -i
    if (k == 16) return make_float2(-a.x, -a.y);    // * -1
    if (k == 24) return make_float2(-a.y, a.x);     // * +i
    return cmuli(a, CS32[k], SN32[k]);
}
// a * e^{+2*pi*i*k/32}
__device__ __forceinline__ float2 twb(float2 a, int k) {
    k &= 31;
    if (k == 0)  return a;
    if (k == 8)  return make_float2(-a.y, a.x);     // * +i
    if (k == 16) return make_float2(-a.x, -a.y);    // * -1
    if (k == 24) return make_float2(a.y, -a.x);     // * -i
    return cmuli(a, CS32[k], -SN32[k]);
}

// radix-4 DIF forward core (no twiddle)
__device__ __forceinline__ void bf4f(float2 x0, float2 x1, float2 x2, float2 x3,
                                     float2& a0, float2& a1, float2& a2, float2& a3) {
    float2 t0 = cadd(x0, x2), t1 = csub(x0, x2);
    float2 t2 = cadd(x1, x3), t3 = csub(x1, x3);
    float2 mi = make_float2(t3.y, -t3.x);                // -i * t3
    a0 = cadd(t0, t2);
    a1 = cadd(t1, mi);
    a2 = csub(t0, t2);
    a3 = csub(t1, mi);
}
// radix-4 inverse core (unscaled)
__device__ __forceinline__ void bf4i(float2 x0, float2 x1, float2 x2, float2 x3,
                                     float2& a0, float2& a1, float2& a2, float2& a3) {
    float2 t0 = cadd(x0, x2), t1 = csub(x0, x2);
    float2 t2 = cadd(x1, x3), t3 = csub(x1, x3);
    float2 pi = make_float2(-t3.y, t3.x);                // +i * t3
    a0 = cadd(t0, t2);
    a1 = cadd(t1, pi);
    a2 = csub(t0, t2);
    a3 = csub(t1, pi);
}

// ---------------- register radix-32 (4*4*2 DIF), external span S = 1<<LS ----
// Twiddles: w_m = b^m * e^{-2*pi*i*m*c/32}; b powers hoisted, rotations literal.
// HALF: x[16..31] implicitly zero on entry.
template<int LS, bool HALF>
__device__ __forceinline__ void fft32_fwd(float2* x, int j) {
    const float C = -6.2831853071795864769f / (float)(1 << (LS + 5));
    float sb, cb;
    __sincosf(C * (float)j, &sb, &cb);
    const float2 b  = make_float2(cb, sb);
    const float2 b2 = cmul(b, b);
    const float2 b3 = cmul(b2, b);
    // stage A: span 8
    #pragma unroll
    for (int c = 0; c < 8; c++) {
        float2 w1 = twf(b,  c);
        float2 w2 = twf(b2, 2 * c);
        float2 w3 = twf(b3, 3 * c);
        float2 a0, a1, a2, a3;
        if (HALF) {
            float2 x0 = x[c], x1 = x[c + 8];
            a0 = cadd(x0, x1);
            a1 = make_float2(x0.x + x1.y, x0.y - x1.x);  // x0 - i*x1
            a2 = csub(x0, x1);
            a3 = make_float2(x0.x - x1.y, x0.y + x1.x);  // x0 + i*x1
        } else {
            bf4f(x[c], x[c+8], x[c+16], x[c+24], a0, a1, a2, a3);
        }
        x[c]      = a0;
        x[c + 8]  = cmul(a1, w1);
        x[c + 16] = cmul(a2, w2);
        x[c + 24] = cmul(a3, w3);
    }
    const float2 b4  = cmul(b2, b2);
    const float2 b8  = cmul(b4, b4);
    const float2 b12 = cmul(b8, b4);
    const float2 b16 = cmul(b8, b8);
    // stage B: span 2; twiddles b4^m * e^{-2*pi*i*4*m*c2/32}
    float2 W1[2], W2[2], W3[2];
    W1[0] = b4;  W2[0] = b8;  W3[0] = b12;
    W1[1] = twf(b4, 4);  W2[1] = twf(b8, 8);  W3[1] = twf(b12, 12);
    #pragma unroll
    for (int g = 0; g < 4; g++) {
        #pragma unroll
        for (int c2 = 0; c2 < 2; c2++) {
            const int i = 8 * g + c2;
            float2 a0, a1, a2, a3;
            bf4f(x[i], x[i+2], x[i+4], x[i+6], a0, a1, a2, a3);
            x[i]     = a0;
            x[i + 2] = cmul(a1, W1[c2]);
            x[i + 4] = cmul(a2, W2[c2]);
            x[i + 6] = cmul(a3, W3[c2]);
        }
    }
    // stage C: radix-2, span 1
    #pragma unroll
    for (int m = 0; m < 16; m++) {
        float2 x0 = x[2*m], x1 = x[2*m + 1];
        x[2*m]     = cadd(x0, x1);
        x[2*m + 1] = cmul(csub(x0, x1), b16);
    }
}

// Inverse (unscaled, gain 32).  HALFOUT: only outputs r<16 are produced.
template<int LS, bool HALFOUT>
__device__ __forceinline__ void fft32_inv(float2* x, int j) {
    const float C = -6.2831853071795864769f / (float)(1 << (LS + 5));
    float sb, cb;
    __sincosf(C * (float)j, &sb, &cb);
    const float2 b   = make_float2(cb, -sb);             // conj base
    const float2 b2  = cmul(b, b);
    const float2 b3  = cmul(b2, b);
    const float2 b4  = cmul(b2, b2);
    const float2 b8  = cmul(b4, b4);
    const float2 b12 = cmul(b8, b4);
    const float2 b16 = cmul(b8, b8);
    // stage C'
    #pragma unroll
    for (int m = 0; m < 16; m++) {
        float2 z1 = cmul(x[2*m + 1], b16);
        float2 x0 = x[2*m];
        x[2*m]     = cadd(x0, z1);
        x[2*m + 1] = csub(x0, z1);
    }
    // stage B'
    float2 W1[2], W2[2], W3[2];
    W1[0] = b4;  W2[0] = b8;  W3[0] = b12;
    W1[1] = twb(b4, 4);  W2[1] = twb(b8, 8);  W3[1] = twb(b12, 12);
    #pragma unroll
    for (int g = 0; g < 4; g++) {
        #pragma unroll
        for (int c2 = 0; c2 < 2; c2++) {
            const int i = 8 * g + c2;
            float2 z0 = x[i];
            float2 z1 = cmul(x[i + 2], W1[c2]);
            float2 z2 = cmul(x[i + 4], W2[c2]);
            float2 z3 = cmul(x[i + 6], W3[c2]);
            bf4i(z0, z1, z2, z3, x[i], x[i+2], x[i+4], x[i+6]);
        }
    }
    // stage A'
    #pragma unroll
    for (int c = 0; c < 8; c++) {
        float2 w1 = twb(b,  c);
        float2 w2 = twb(b2, 2 * c);
        float2 w3 = twb(b3, 3 * c);
        float2 z0 = x[c];
        float2 z1 = cmul(x[c + 8],  w1);
        float2 z2 = cmul(x[c + 16], w2);
        float2 z3 = cmul(x[c + 24], w3);
        if (HALFOUT) {
            float2 t0 = cadd(z0, z2), t1 = csub(z0, z2);
            float2 t2 = cadd(z1, z3), t3 = csub(z1, z3);
            float2 pi = make_float2(-t3.y, t3.x);
            x[c]     = cadd(t0, t2);
            x[c + 8] = cadd(t1, pi);
        } else {
            bf4i(z0, z1, z2, z3, x[c], x[c+8], x[c+16], x[c+24]);
        }
    }
}

// ---------------- 16-point cores: ALL twiddles literal ----------------------
__device__ __forceinline__ void fft16c_fwd(float2* x) {
    #pragma unroll
    for (int c = 0; c < 4; c++) {
        float2 a0, a1, a2, a3;
        bf4f(x[c], x[c+4], x[c+8], x[c+12], a0, a1, a2, a3);
        x[c]      = a0;
        x[c + 4]  = twf(a1, 2 * c);
        x[c + 8]  = twf(a2, 4 * c);
        x[c + 12] = twf(a3, 6 * c);
    }
    #pragma unroll
    for (int m = 0; m < 4; m++) {
        float2 a0, a1, a2, a3;
        bf4f(x[4*m], x[4*m+1], x[4*m+2], x[4*m+3], a0, a1, a2, a3);
        x[4*m] = a0; x[4*m+1] = a1; x[4*m+2] = a2; x[4*m+3] = a3;
    }
}
__device__ __forceinline__ void fft16c_inv(float2* x) {
    #pragma unroll
    for (int m = 0; m < 4; m++) {
        float2 a0, a1, a2, a3;
        bf4i(x[4*m], x[4*m+1], x[4*m+2], x[4*m+3], a0, a1, a2, a3);
        x[4*m] = a0; x[4*m+1] = a1; x[4*m+2] = a2; x[4*m+3] = a3;
    }
    #pragma unroll
    for (int c = 0; c < 4; c++) {
        float2 z1 = twb(x[c + 4],  2 * c);
        float2 z2 = twb(x[c + 8],  4 * c);
        float2 z3 = twb(x[c + 12], 6 * c);
        bf4i(x[c], z1, z2, z3, x[c], x[c+4], x[c+8], x[c+12]);
    }
}

// ---------------- filter MLP stages 1-3 --------------------------------------
__global__ void mlp_kernel(const float* __restrict__ z, const float* __restrict__ freq,
                           const float* __restrict__ W1, const float* __restrict__ b1,
                           const float* __restrict__ W2, const float* __restrict__ b2,
                           const float* __restrict__ W3, const float* __restrict__ b3) {
    __shared__ float zs[4][EMB];
    __shared__ float as[4][FO];
    __shared__ float bs[4][FO];
    const int tid = threadIdx.x;
    const int lg  = tid >> 6;
    const int f   = tid & 63;
    const int l   = blockIdx.x * 4 + lg;

    if (f < EMB) zs[lg][f] = z[l * EMB + f];
    __syncthreads();

    const float fr = freq[f];

    float acc = b1[f];
    #pragma unroll
    for (int e = 0; e < EMB; e++) acc += zs[lg][e] * W1[e * FO + f];
    as[lg][f] = sinf(fr * acc);
    __syncthreads();

    acc = b2[f];
    #pragma unroll
    for (int e = 0; e < FO; e++) acc += as[lg][e] * W2[e * FO + f];
    bs[lg][f] = sinf(fr * acc);
    __syncthreads();

    acc = b3[f];
    #pragma unroll
    for (int e = 0; e < FO; e++) acc += bs[lg][e] * W3[e * FO + f];
    g_S[l * FO + f] = sinf(fr * acc);
}

// ---------------- output projection + exponential modulation ----------------
// expf(-t_l * a) is geometric in l (t = linspace step 1/8191):
// 2 expf per thread instead of 16 (MUFU-bound -> FMA-bound).
__global__ void filt_kernel(const float* __restrict__ Wout, const float* __restrict__ t,
                            const float* __restrict__ deltas) {
    __shared__ float Ss[32][FO];
    __shared__ float Ws[FO][128];
    const int tid = threadIdx.x;
    const int l0  = blockIdx.x * 32;
    const int d0  = blockIdx.y * 128;

    for (int i = tid; i < 32 * FO; i += 256)
        Ss[i >> 6][i & 63] = g_S[(l0 + (i >> 6)) * FO + (i & 63)];
    for (int i = tid; i < FO * 128; i += 256)
        Ws[i >> 7][i & 127] = Wout[(i >> 7) * DM + d0 + (i & 127)];
    __syncthreads();

    const int dl  = tid & 127;
    const int lgp = tid >> 7;
    float acc[16];
    #pragma unroll
    for (int i = 0; i < 16; i++) acc[i] = 0.0f;
    #pragma unroll
    for (int f = 0; f < FO; f++) {
        const float w = Ws[f][dl];
        #pragma unroll
        for (int i = 0; i < 16; i++) acc[i] += Ss[lgp * 16 + i][f] * w;
    }
    const int d = d0 + dl;
    const float ad = fabsf(deltas[d]);
    const int lbase = l0 + lgp * 16;
    float e = expf(-t[lbase] * ad);
    const float rr = expf(-ad * (1.0f / 8191.0f));
    float* kout = g_k + (size_t)d * LSEQ + lbase;
    #pragma unroll
    for (int i = 0; i < 16; i++) {
        kout[i] = acc[i] * (e + SHIFT_C);
        e *= rr;
    }
}

// ---------------- kernel spectra, 2 channels per FFT (Hermitian split) ------
// Storage map (derived): s = s3 + 16*s2 + 512*s1 holds f = p1 + 32*p2 + 1024*p3
// where s_i = digit-reversal of p_i (radix 4*4*2 for the 32s, 4*4 swap for 16).
// Conjugate partner -f: lowest NONZERO digit group gets (+1)-complement, higher
// groups pure complement.  In STORAGE indices:
//   pure complement:  s' = 31 - s   (32-groups),  15 - s3  (16-group)
//   (+1)-complement:  s' = prt32(s) = 39-s (s>=8) | 9-s (2<=s<=7) | 1 (s==1)
//   16-group (+1)-complement: 19-s3 (s3>=4) | 4-s3 (1<=s3<=3) | 0 (s3==0)
__device__ __forceinline__ int prt32(int m) {
    return (m >= 8) ? (39 - m) : ((m >= 2) ? (9 - m) : 1);
}

__global__ void __launch_bounds__(NT, 1)
kf_kernel(const float* __restrict__ Dbias) {
    extern __shared__ float2 d[];
    const int tid = threadIdx.x;
    const int cp  = blockIdx.x;                          // channel pair
    const int chA = 2 * cp, chB = 2 * cp + 1;

    const float* krowA = g_k + (size_t)chA * LSEQ;
    const float* krowB = g_k + (size_t)chB * LSEQ;
    const int jb = tid + (tid >> 4);                     // PHYS(tid)

    // P1: radix-32, S=512; pack kA + i*kB; top half zero
    {
        float2 xv[32];
        #pragma unroll
        for (int r = 0; r < 16; r++) {
            const int i = tid + (r << 9);
            xv[r] = make_float2(krowA[i], krowB[i]);
        }
        fft32_fwd<9, true>(xv, tid);
        #pragma unroll
        for (int r = 0; r < 32; r++) d[jb + 544 * r] = xv[r];
    }
    __syncthreads();

    const int j2 = tid & 15;
    const int b0 = (tid >> 4) * 544 + j2;

    // P2: radix-32, S=16
    {
        float2 xv[32];
        #pragma unroll
        for (int r = 0; r < 32; r++) xv[r] = d[b0 + 17 * r];
        fft32_fwd<4, false>(xv, j2);
        #pragma unroll
        for (int r = 0; r < 32; r++) d[b0 + 17 * r] = xv[r];
    }
    __syncthreads();

    // P3: const-twiddle fwd16, store back to smem (full spectrum needed for split)
    #pragma unroll
    for (int k = 0; k < 2; k++) {
        const int q  = tid + k * NT;
        const int pb = 17 * q;
        float2 xv[16];
        #pragma unroll
        for (int r = 0; r < 16; r++) xv[r] = d[pb + r];
        fft16c_fwd(xv);
        #pragma unroll
        for (int r = 0; r < 16; r++) d[pb + r] = xv[r];
    }
    __syncthreads();

    // P4: Hermitian unpack + bake + write both channels
    // KA = (Z + conj(Zp))/2,  KB = -i*(Z - conj(Zp))/2
    const float sc = 1.0f / (float)NFFT;
    const float DA = Dbias[chA], DB = Dbias[chB];
    float2* outA = g_Kf + (size_t)chA * NFFT;
    float2* outB = g_Kf + (size_t)chB * NFFT;
    #pragma unroll
    for (int k = 0; k < 2; k++) {
        const int q  = tid + k * NT;
        const int m2 = q & 31, m1 = q >> 5;
        int qb;
        if (m1 >= 1)      qb = (31 - m2) + 32 * prt32(m1);
        else if (m2 >= 1) qb = prt32(m2);
        else              qb = 0;
        const bool special = (q == 0);                   // q==0 block: 16-group +1-complement
        const int pb = 17 * q, pbb = 17 * qb;
        float2 za[16], zp[16];
        #pragma unroll
        for (int r = 0; r < 16; r++) za[r] = d[pb + r];
        #pragma unroll
        for (int m3 = 0; m3 < 16; m3++) {
            int m3b;
            if (!special) m3b = 15 - m3;
            else          m3b = (m3 == 0) ? 0 : ((m3 >= 4) ? (19 - m3) : (4 - m3));
            zp[m3] = d[pbb + m3b];                       // partner loaded pre-remapped
        }
        float4* oA = reinterpret_cast<float4*>(outA + 16 * q);
        float4* oB = reinterpret_cast<float4*>(outB + 16 * q);
        #pragma unroll
        for (int i = 0; i < 8; i++) {
            float kax[2], kay[2], kbx[2], kby[2];
            #pragma unroll
            for (int h = 0; h < 2; h++) {
                const int m3 = 2 * i + h;
                const float a = za[m3].x, bb = za[m3].y;
                const float c = zp[m3].x, dd = zp[m3].y;
                kax[h] = 0.5f * (a + c);   kay[h] = 0.5f * (bb - dd);
                kbx[h] = 0.5f * (bb + dd); kby[h] = 0.5f * (c - a);
            }
            oA[i] = make_float4((kax[0] + DA) * sc, kay[0] * sc,
                                (kax[1] + DA) * sc, kay[1] * sc);
            oB[i] = make_float4((kbx[0] + DB) * sc, kby[0] * sc,
                                (kbx[1] + DB) * sc, kby[1] * sc);
        }
    }
}

// ---------------- conv ------------------------------------------------------
// grid = dim3(2, DM): the two batch-pair CTAs of a channel are adjacent in
// linear block order -> co-resident -> second Kf read hits L2.
__global__ void __launch_bounds__(NT, 1)
conv_kernel(const float* __restrict__ x, float* __restrict__ out) {
    extern __shared__ float2 d[];
    const int tid = threadIdx.x;
    const int ch  = blockIdx.y;
    const int p   = blockIdx.x;                          // batch pair

    const float* u0 = x + ((size_t)(2*p)     * DM + ch) * LSEQ;
    const float* u1 = x + ((size_t)(2*p + 1) * DM + ch) * LSEQ;
    const float2* kf = g_Kf + (size_t)ch * NFFT;

    // prefetch this thread's Kf lines into L2 (consumed in P3, ~2500 cyc away)
    asm volatile("prefetch.global.L2 [%0];" :: "l"(kf + 16 * tid));
    asm volatile("prefetch.global.L2 [%0];" :: "l"(kf + 16 * (tid + NT)));

    const int jb = tid + (tid >> 4);

    // P1 fwd: radix-32, S=512; pack u0 + i*u1; top half zero
    {
        float2 xv[32];
        #pragma unroll
        for (int r = 0; r < 16; r++) {
            const int i = tid + (r << 9);
            xv[r] = make_float2(u0[i], u1[i]);
        }
        fft32_fwd<9, true>(xv, tid);
        #pragma unroll
        for (int r = 0; r < 32; r++) d[jb + 544 * r] = xv[r];
    }
    __syncthreads();

    const int j2 = tid & 15;
    const int b0 = (tid >> 4) * 544 + j2;

    // P2 fwd: radix-32, S=16
    {
        float2 xv[32];
        #pragma unroll
        for (int r = 0; r < 32; r++) xv[r] = d[b0 + 17 * r];
        fft32_fwd<4, false>(xv, j2);
        #pragma unroll
        for (int r = 0; r < 32; r++) d[b0 + 17 * r] = xv[r];
    }
    __syncthreads();

    // P3: const-twiddle fwd16 -> * Kf (D baked in) -> const-twiddle inv16
    #pragma unroll
    for (int k = 0; k < 2; k++) {
        const int q  = tid + k * NT;
        const int pb = 17 * q;
        float4 kreg[8];
        const float4* kf4 = reinterpret_cast<const float4*>(kf + 16 * q);
        #pragma unroll
        for (int i = 0; i < 8; i++) kreg[i] = kf4[i];    // prefetch over fwd16
        float2 xv[16];
        #pragma unroll
        for (int r = 0; r < 16; r++) xv[r] = d[pb + r];
        fft16c_fwd(xv);
        #pragma unroll
        for (int i = 0; i < 8; i++) {
            xv[2*i]   = cmul(xv[2*i],   make_float2(kreg[i].x, kreg[i].y));
            xv[2*i+1] = cmul(xv[2*i+1], make_float2(kreg[i].z, kreg[i].w));
        }
        fft16c_inv(xv);
        #pragma unroll
        for (int r = 0; r < 16; r++) d[pb + r] = xv[r];
    }
    __syncthreads();

    // P2' inv
    {
        float2 xv[32];
        #pragma unroll
        for (int r = 0; r < 32; r++) xv[r] = d[b0 + 17 * r];
        fft32_inv<4, false>(xv, j2);
        #pragma unroll
        for (int r = 0; r < 32; r++) d[b0 + 17 * r] = xv[r];
    }
    __syncthreads();

    // P1' inv: half output, direct global store
    float* o0 = out + ((size_t)(2*p)     * DM + ch) * LSEQ;
    float* o1 = out + ((size_t)(2*p + 1) * DM + ch) * LSEQ;
    {
        float2 xv[32];
        #pragma unroll
        for (int r = 0; r < 32; r++) xv[r] = d[jb + 544 * r];
        fft32_inv<9, true>(xv, tid);
        #pragma unroll
        for (int r = 0; r < 16; r++) {
            const int i = tid + (r << 9);
            o0[i] = xv[r].x;
            o1[i] = xv[r].y;
        }
    }
}

// ---------------- launch ----------------------------------------------------
// Input order (metadata): x, z, t, freq, W1, b1, W2, b2, W3, b3, Wout, deltas, D
extern "C" void kernel_launch(void* const* d_in, const int* in_sizes, int n_in,
                              void* d_out, int out_size) {
    (void)in_sizes; (void)n_in; (void)out_size;
    const float* x      = (const float*)d_in[0];
    const float* z      = (const float*)d_in[1];
    const float* t      = (const float*)d_in[2];
    const float* freq   = (const float*)d_in[3];
    const float* W1     = (const float*)d_in[4];
    const float* b1     = (const float*)d_in[5];
    const float* W2     = (const float*)d_in[6];
    const float* b2     = (const float*)d_in[7];
    const float* W3     = (const float*)d_in[8];
    const float* b3     = (const float*)d_in[9];
    const float* Wout   = (const float*)d_in[10];
    const float* deltas = (const float*)d_in[11];
    const float* Dbias  = (const float*)d_in[12];
    float* out = (float*)d_out;

    cudaFuncSetAttribute(kf_kernel,   cudaFuncAttributeMaxDynamicSharedMemorySize, SMEM_BYTES);
    cudaFuncSetAttribute(conv_kernel, cudaFuncAttributeMaxDynamicSharedMemorySize, SMEM_BYTES);

    mlp_kernel<<<LSEQ / 4, 256>>>(z, freq, W1, b1, W2, b2, W3, b3);
    filt_kernel<<<dim3(LSEQ / 32, DM / 128), 256>>>(Wout, t, deltas);
    kf_kernel<<<DM / 2, NT, SMEM_BYTES>>>(Dbias);
    conv_kernel<<<dim3(2, DM), NT, SMEM_BYTES>>>(x, out);
}

// round 13
// speedup vs baseline: 1.0318x; 1.0318x over previous
#include <cuda_runtime.h>
#include <math.h>

// Problem constants
#define LSEQ 8192
#define NFFT 16384          // 2*LSEQ = 32*32*16
#define DM   768
#define EMB  33
#define FO   64
#define SHIFT_C 0.05f
#define NT   512            // FFT threads per CTA

// Pad 1 float2 per 16: PHYS(i) = i + (i>>4).  (verified conflict-free R5)
#define DPAD 17408
#define SMEM_BYTES (DPAD * (int)sizeof(float2))          // 139264 B

// ---------------- scratch (device globals: no allocations allowed) ----------
__device__ float g_S[LSEQ * FO];                         // post-MLP activations
__device__ float g_k[DM * LSEQ];                         // filter k[d][l]
__device__ __align__(16) float2 g_Kf[(size_t)DM * NFFT]; // (spectrum + D)/N, scrambled

// cos / (-sin) of 2*pi*k/32 as compile-time constants -> immediate-form FFMA
__device__ static constexpr float CS32[32] = {
    1.0f,                   0.98078528040323044f,  0.92387953251128674f,  0.83146961230254524f,
    0.70710678118654752f,   0.55557023301960222f,  0.38268343236508977f,  0.19509032201612827f,
    0.0f,                  -0.19509032201612827f, -0.38268343236508977f, -0.55557023301960222f,
   -0.70710678118654752f,  -0.83146961230254524f, -0.92387953251128674f, -0.98078528040323044f,
   -1.0f,                  -0.98078528040323044f, -0.92387953251128674f, -0.83146961230254524f,
   -0.70710678118654752f,  -0.55557023301960222f, -0.38268343236508977f, -0.19509032201612827f,
    0.0f,                   0.19509032201612827f,  0.38268343236508977f,  0.55557023301960222f,
    0.70710678118654752f,   0.83146961230254524f,  0.92387953251128674f,  0.98078528040323044f
};
__device__ static constexpr float SN32[32] = {     // = sin(-2*pi*k/32)
    0.0f,                  -0.19509032201612827f, -0.38268343236508977f, -0.55557023301960222f,
   -0.70710678118654752f,  -0.83146961230254524f, -0.92387953251128674f, -0.98078528040323044f,
   -1.0f,                  -0.98078528040323044f, -0.92387953251128674f, -0.83146961230254524f,
   -0.70710678118654752f,  -0.55557023301960222f, -0.38268343236508977f, -0.19509032201612827f,
    0.0f,                   0.19509032201612827f,  0.38268343236508977f,  0.55557023301960222f,
    0.70710678118654752f,   0.83146961230254524f,  0.92387953251128674f,  0.98078528040323044f,
    1.0f,                   0.98078528040323044f,  0.92387953251128674f,  0.83146961230254524f,
    0.70710678118654752f,   0.55557023301960222f,  0.38268343236508977f,  0.19509032201612827f
};

// ---------------- complex helpers ----------------
__device__ __forceinline__ float2 cadd(float2 a, float2 b){ return make_float2(a.x+b.x, a.y+b.y); }
__device__ __forceinline__ float2 csub(float2 a, float2 b){ return make_float2(a.x-b.x, a.y-b.y); }
__device__ __forceinline__ float2 cmul(float2 a, float2 b){
    return make_float2(a.x*b.x - a.y*b.y, a.x*b.y + a.y*b.x);
}
// multiply by compile-time literal (wx, wy): 2 FMUL-imm + 2 FFMA-imm (rt=1)
__device__ __forceinline__ float2 cmuli(float2 a, float wx, float wy) {
    return make_float2(fmaf(a.y, -wy, a.x * wx), fmaf(a.y, wx, a.x * wy));
}
// a * e^{-2*pi*i*k/32}; k folded to constant under #pragma unroll
__device__ __forceinline__ float2 twf(float2 a, int k) {
    k &= 31;
    if (k == 0)  return a;
    if (k == 8)  return make_float2(a.y, -a.x);     // * -i
    if (k == 16) return make_float2(-a.x, -a.y);    // * -1
    if (k == 24) return make_float2(-a.y, a.x);     // * +i
    return cmuli(a, CS32[k], SN32[k]);
}
// a * e^{+2*pi*i*k/32}
__device__ __forceinline__ float2 twb(float2 a, int k) {
    k &= 31;
    if (k == 0)  return a;
    if (k == 8)  return make_float2(-a.y, a.x);     // * +i
    if (k == 16) return make_float2(-a.x, -a.y);    // * -1
    if (k == 24) return make_float2(a.y, -a.x);     // * -i
    return cmuli(a, CS32[k], -SN32[k]);
}

// radix-4 DIF forward core (no twiddle)
__device__ __forceinline__ void bf4f(float2 x0, float2 x1, float2 x2, float2 x3,
                                     float2& a0, float2& a1, float2& a2, float2& a3) {
    float2 t0 = cadd(x0, x2), t1 = csub(x0, x2);
    float2 t2 = cadd(x1, x3), t3 = csub(x1, x3);
    float2 mi = make_float2(t3.y, -t3.x);                // -i * t3
    a0 = cadd(t0, t2);
    a1 = cadd(t1, mi);
    a2 = csub(t0, t2);
    a3 = csub(t1, mi);
}
// radix-4 inverse core (unscaled)
__device__ __forceinline__ void bf4i(float2 x0, float2 x1, float2 x2, float2 x3,
                                     float2& a0, float2& a1, float2& a2, float2& a3) {
    float2 t0 = cadd(x0, x2), t1 = csub(x0, x2);
    float2 t2 = cadd(x1, x3), t3 = csub(x1, x3);
    float2 pi = make_float2(-t3.y, t3.x);                // +i * t3
    a0 = cadd(t0, t2);
    a1 = cadd(t1, pi);
    a2 = csub(t0, t2);
    a3 = csub(t1, pi);
}

// ---------------- register radix-32 (4*4*2 DIF), external span S = 1<<LS ----
// Twiddles: w_m = b^m * e^{-2*pi*i*m*c/32}; b powers hoisted, rotations literal.
// HALF: x[16..31] implicitly zero on entry.
template<int LS, bool HALF>
__device__ __forceinline__ void fft32_fwd(float2* x, int j) {
    const float C = -6.2831853071795864769f / (float)(1 << (LS + 5));
    float sb, cb;
    __sincosf(C * (float)j, &sb, &cb);
    const float2 b  = make_float2(cb, sb);
    const float2 b2 = cmul(b, b);
    const float2 b3 = cmul(b2, b);
    // stage A: span 8
    #pragma unroll
    for (int c = 0; c < 8; c++) {
        float2 w1 = twf(b,  c);
        float2 w2 = twf(b2, 2 * c);
        float2 w3 = twf(b3, 3 * c);
        float2 a0, a1, a2, a3;
        if (HALF) {
            float2 x0 = x[c], x1 = x[c + 8];
            a0 = cadd(x0, x1);
            a1 = make_float2(x0.x + x1.y, x0.y - x1.x);  // x0 - i*x1
            a2 = csub(x0, x1);
            a3 = make_float2(x0.x - x1.y, x0.y + x1.x);  // x0 + i*x1
        } else {
            bf4f(x[c], x[c+8], x[c+16], x[c+24], a0, a1, a2, a3);
        }
        x[c]      = a0;
        x[c + 8]  = cmul(a1, w1);
        x[c + 16] = cmul(a2, w2);
        x[c + 24] = cmul(a3, w3);
    }
    const float2 b4  = cmul(b2, b2);
    const float2 b8  = cmul(b4, b4);
    const float2 b12 = cmul(b8, b4);
    const float2 b16 = cmul(b8, b8);
    // stage B: span 2; twiddles b4^m * e^{-2*pi*i*4*m*c2/32}
    float2 W1[2], W2[2], W3[2];
    W1[0] = b4;  W2[0] = b8;  W3[0] = b12;
    W1[1] = twf(b4, 4);  W2[1] = twf(b8, 8);  W3[1] = twf(b12, 12);
    #pragma unroll
    for (int g = 0; g < 4; g++) {
        #pragma unroll
        for (int c2 = 0; c2 < 2; c2++) {
            const int i = 8 * g + c2;
            float2 a0, a1, a2, a3;
            bf4f(x[i], x[i+2], x[i+4], x[i+6], a0, a1, a2, a3);
            x[i]     = a0;
            x[i + 2] = cmul(a1, W1[c2]);
            x[i + 4] = cmul(a2, W2[c2]);
            x[i + 6] = cmul(a3, W3[c2]);
        }
    }
    // stage C: radix-2, span 1
    #pragma unroll
    for (int m = 0; m < 16; m++) {
        float2 x0 = x[2*m], x1 = x[2*m + 1];
        x[2*m]     = cadd(x0, x1);
        x[2*m + 1] = cmul(csub(x0, x1), b16);
    }
}

// Inverse (unscaled, gain 32).  HALFOUT: only outputs r<16 are produced.
template<int LS, bool HALFOUT>
__device__ __forceinline__ void fft32_inv(float2* x, int j) {
    const float C = -6.2831853071795864769f / (float)(1 << (LS + 5));
    float sb, cb;
    __sincosf(C * (float)j, &sb, &cb);
    const float2 b   = make_float2(cb, -sb);             // conj base
    const float2 b2  = cmul(b, b);
    const float2 b3  = cmul(b2, b);
    const float2 b4  = cmul(b2, b2);
    const float2 b8  = cmul(b4, b4);
    const float2 b12 = cmul(b8, b4);
    const float2 b16 = cmul(b8, b8);
    // stage C'
    #pragma unroll
    for (int m = 0; m < 16; m++) {
        float2 z1 = cmul(x[2*m + 1], b16);
        float2 x0 = x[2*m];
        x[2*m]     = cadd(x0, z1);
        x[2*m + 1] = csub(x0, z1);
    }
    // stage B'
    float2 W1[2], W2[2], W3[2];
    W1[0] = b4;  W2[0] = b8;  W3[0] = b12;
    W1[1] = twb(b4, 4);  W2[1] = twb(b8, 8);  W3[1] = twb(b12, 12);
    #pragma unroll
    for (int g = 0; g < 4; g++) {
        #pragma unroll
        for (int c2 = 0; c2 < 2; c2++) {
            const int i = 8 * g + c2;
            float2 z0 = x[i];
            float2 z1 = cmul(x[i + 2], W1[c2]);
            float2 z2 = cmul(x[i + 4], W2[c2]);
            float2 z3 = cmul(x[i + 6], W3[c2]);
            bf4i(z0, z1, z2, z3, x[i], x[i+2], x[i+4], x[i+6]);
        }
    }
    // stage A'
    #pragma unroll
    for (int c = 0; c < 8; c++) {
        float2 w1 = twb(b,  c);
        float2 w2 = twb(b2, 2 * c);
        float2 w3 = twb(b3, 3 * c);
        float2 z0 = x[c];
        float2 z1 = cmul(x[c + 8],  w1);
        float2 z2 = cmul(x[c + 16], w2);
        float2 z3 = cmul(x[c + 24], w3);
        if (HALFOUT) {
            float2 t0 = cadd(z0, z2), t1 = csub(z0, z2);
            float2 t2 = cadd(z1, z3), t3 = csub(z1, z3);
            float2 pi = make_float2(-t3.y, t3.x);
            x[c]     = cadd(t0, t2);
            x[c + 8] = cadd(t1, pi);
        } else {
            bf4i(z0, z1, z2, z3, x[c], x[c+8], x[c+16], x[c+24]);
        }
    }
}

// ---------------- 16-point cores: ALL twiddles literal ----------------------
__device__ __forceinline__ void fft16c_fwd(float2* x) {
    #pragma unroll
    for (int c = 0; c < 4; c++) {
        float2 a0, a1, a2, a3;
        bf4f(x[c], x[c+4], x[c+8], x[c+12], a0, a1, a2, a3);
        x[c]      = a0;
        x[c + 4]  = twf(a1, 2 * c);
        x[c + 8]  = twf(a2, 4 * c);
        x[c + 12] = twf(a3, 6 * c);
    }
    #pragma unroll
    for (int m = 0; m < 4; m++) {
        float2 a0, a1, a2, a3;
        bf4f(x[4*m], x[4*m+1], x[4*m+2], x[4*m+3], a0, a1, a2, a3);
        x[4*m] = a0; x[4*m+1] = a1; x[4*m+2] = a2; x[4*m+3] = a3;
    }
}
__device__ __forceinline__ void fft16c_inv(float2* x) {
    #pragma unroll
    for (int m = 0; m < 4; m++) {
        float2 a0, a1, a2, a3;
        bf4i(x[4*m], x[4*m+1], x[4*m+2], x[4*m+3], a0, a1, a2, a3);
        x[4*m] = a0; x[4*m+1] = a1; x[4*m+2] = a2; x[4*m+3] = a3;
    }
    #pragma unroll
    for (int c = 0; c < 4; c++) {
        float2 z1 = twb(x[c + 4],  2 * c);
        float2 z2 = twb(x[c + 8],  4 * c);
        float2 z3 = twb(x[c + 12], 6 * c);
        bf4i(x[c], z1, z2, z3, x[c], x[c+4], x[c+8], x[c+12]);
    }
}

// ---------------- filter MLP stages 1-3 --------------------------------------
__global__ void mlp_kernel(const float* __restrict__ z, const float* __restrict__ freq,
                           const float* __restrict__ W1, const float* __restrict__ b1,
                           const float* __restrict__ W2, const float* __restrict__ b2,
                           const float* __restrict__ W3, const float* __restrict__ b3) {
    __shared__ float zs[4][EMB];
    __shared__ float as[4][FO];
    __shared__ float bs[4][FO];
    const int tid = threadIdx.x;
    const int lg  = tid >> 6;
    const int f   = tid & 63;
    const int l   = blockIdx.x * 4 + lg;

    if (f < EMB) zs[lg][f] = z[l * EMB + f];
    __syncthreads();

    const float fr = freq[f];

    float acc = b1[f];
    #pragma unroll
    for (int e = 0; e < EMB; e++) acc += zs[lg][e] * W1[e * FO + f];
    as[lg][f] = sinf(fr * acc);
    __syncthreads();

    acc = b2[f];
    #pragma unroll
    for (int e = 0; e < FO; e++) acc += as[lg][e] * W2[e * FO + f];
    bs[lg][f] = sinf(fr * acc);
    __syncthreads();

    acc = b3[f];
    #pragma unroll
    for (int e = 0; e < FO; e++) acc += bs[lg][e] * W3[e * FO + f];
    g_S[l * FO + f] = sinf(fr * acc);
}

// ---------------- output projection + exponential modulation ----------------
// expf(-t_l * a) is geometric in l (t = linspace step 1/8191):
// 2 expf per thread instead of 16 (MUFU-bound -> FMA-bound).
__global__ void filt_kernel(const float* __restrict__ Wout, const float* __restrict__ t,
                            const float* __restrict__ deltas) {
    __shared__ float Ss[32][FO];
    __shared__ float Ws[FO][128];
    const int tid = threadIdx.x;
    const int l0  = blockIdx.x * 32;
    const int d0  = blockIdx.y * 128;

    for (int i = tid; i < 32 * FO; i += 256)
        Ss[i >> 6][i & 63] = g_S[(l0 + (i >> 6)) * FO + (i & 63)];
    for (int i = tid; i < FO * 128; i += 256)
        Ws[i >> 7][i & 127] = Wout[(i >> 7) * DM + d0 + (i & 127)];
    __syncthreads();

    const int dl  = tid & 127;
    const int lgp = tid >> 7;
    float acc[16];
    #pragma unroll
    for (int i = 0; i < 16; i++) acc[i] = 0.0f;
    #pragma unroll
    for (int f = 0; f < FO; f++) {
        const float w = Ws[f][dl];
        #pragma unroll
        for (int i = 0; i < 16; i++) acc[i] += Ss[lgp * 16 + i][f] * w;
    }
    const int d = d0 + dl;
    const float ad = fabsf(deltas[d]);
    const int lbase = l0 + lgp * 16;
    float e = expf(-t[lbase] * ad);
    const float rr = expf(-ad * (1.0f / 8191.0f));
    float* kout = g_k + (size_t)d * LSEQ + lbase;
    #pragma unroll
    for (int i = 0; i < 16; i++) {
        kout[i] = acc[i] * (e + SHIFT_C);
        e *= rr;
    }
}

// ---------------- kernel spectrum (+D baked in), per-channel (R9) -----------
__global__ void __launch_bounds__(NT, 1)
kf_kernel(const float* __restrict__ Dbias) {
    extern __shared__ float2 d[];
    const int tid = threadIdx.x;
    const int ch  = blockIdx.x;

    const float* krow = g_k + (size_t)ch * LSEQ;
    const int jb = tid + (tid >> 4);                     // PHYS(tid)

    // P1: radix-32, S=512; top half zero
    {
        float2 xv[32];
        #pragma unroll
        for (int r = 0; r < 16; r++)
            xv[r] = make_float2(krow[tid + (r << 9)], 0.0f);
        fft32_fwd<9, true>(xv, tid);
        #pragma unroll
        for (int r = 0; r < 32; r++) d[jb + 544 * r] = xv[r];
    }
    __syncthreads();

    const int j2 = tid & 15;
    const int b0 = (tid >> 4) * 544 + j2;

    // P2: radix-32, S=16
    {
        float2 xv[32];
        #pragma unroll
        for (int r = 0; r < 32; r++) xv[r] = d[b0 + 17 * r];
        fft32_fwd<4, false>(xv, j2);
        #pragma unroll
        for (int r = 0; r < 32; r++) d[b0 + 17 * r] = xv[r];
    }
    __syncthreads();

    // P3: const-twiddle fwd16 + bake (spec + D)/N, store to g_Kf
    float2* outp = g_Kf + (size_t)ch * NFFT;
    const float sc = 1.0f / (float)NFFT;
    const float Dd = Dbias[ch];
    #pragma unroll
    for (int k = 0; k < 2; k++) {
        const int q  = tid + k * NT;
        const int pb = 17 * q;                           // PHYS(16q)
        float2 xv[16];
        #pragma unroll
        for (int r = 0; r < 16; r++) xv[r] = d[pb + r];
        fft16c_fwd(xv);
        float4* o4 = reinterpret_cast<float4*>(outp + 16 * q);
        #pragma unroll
        for (int i = 0; i < 8; i++) {
            o4[i] = make_float4((xv[2*i].x + Dd) * sc, xv[2*i].y * sc,
                                (xv[2*i+1].x + Dd) * sc, xv[2*i+1].y * sc);
        }
    }
}

// ---------------- conv ------------------------------------------------------
// grid = dim3(2, DM): the two batch-pair CTAs of a channel are adjacent in
// linear block order -> co-resident -> second Kf read hits L2.
__global__ void __launch_bounds__(NT, 1)
conv_kernel(const float* __restrict__ x, float* __restrict__ out) {
    extern __shared__ float2 d[];
    const int tid = threadIdx.x;
    const int ch  = blockIdx.y;
    const int p   = blockIdx.x;                          // batch pair

    const float* u0 = x + ((size_t)(2*p)     * DM + ch) * LSEQ;
    const float* u1 = x + ((size_t)(2*p + 1) * DM + ch) * LSEQ;
    const float2* kf = g_Kf + (size_t)ch * NFFT;

    // prefetch this thread's Kf lines into L2 (consumed in P3, ~2500 cyc away)
    asm volatile("prefetch.global.L2 [%0];" :: "l"(kf + 16 * tid));
    asm volatile("prefetch.global.L2 [%0];" :: "l"(kf + 16 * (tid + NT)));

    const int jb = tid + (tid >> 4);

    // P1 fwd: radix-32, S=512; pack u0 + i*u1; top half zero
    {
        float2 xv[32];
        #pragma unroll
        for (int r = 0; r < 16; r++) {
            const int i = tid + (r << 9);
            xv[r] = make_float2(u0[i], u1[i]);
        }
        fft32_fwd<9, true>(xv, tid);
        #pragma unroll
        for (int r = 0; r < 32; r++) d[jb + 544 * r] = xv[r];
    }
    __syncthreads();

    const int j2 = tid & 15;
    const int b0 = (tid >> 4) * 544 + j2;

    // P2 fwd: radix-32, S=16
    {
        float2 xv[32];
        #pragma unroll
        for (int r = 0; r < 32; r++) xv[r] = d[b0 + 17 * r];
        fft32_fwd<4, false>(xv, j2);
        #pragma unroll
        for (int r = 0; r < 32; r++) d[b0 + 17 * r] = xv[r];
    }
    __syncthreads();

    // P3: const-twiddle fwd16 -> * Kf (D baked in) -> const-twiddle inv16
    #pragma unroll
    for (int k = 0; k < 2; k++) {
        const int q  = tid + k * NT;
        const int pb = 17 * q;
        float4 kreg[8];
        const float4* kf4 = reinterpret_cast<const float4*>(kf + 16 * q);
        #pragma unroll
        for (int i = 0; i < 8; i++) kreg[i] = kf4[i];    // prefetch over fwd16
        float2 xv[16];
        #pragma unroll
        for (int r = 0; r < 16; r++) xv[r] = d[pb + r];
        fft16c_fwd(xv);
        #pragma unroll
        for (int i = 0; i < 8; i++) {
            xv[2*i]   = cmul(xv[2*i],   make_float2(kreg[i].x, kreg[i].y));
            xv[2*i+1] = cmul(xv[2*i+1], make_float2(kreg[i].z, kreg[i].w));
        }
        fft16c_inv(xv);
        #pragma unroll
        for (int r = 0; r < 16; r++) d[pb + r] = xv[r];
    }
    __syncthreads();

    // P2' inv
    {
        float2 xv[32];
        #pragma unroll
        for (int r = 0; r < 32; r++) xv[r] = d[b0 + 17 * r];
        fft32_inv<4, false>(xv, j2);
        #pragma unroll
        for (int r = 0; r < 32; r++) d[b0 + 17 * r] = xv[r];
    }
    __syncthreads();

    // P1' inv: half output, direct global store
    float* o0 = out + ((size_t)(2*p)     * DM + ch) * LSEQ;
    float* o1 = out + ((size_t)(2*p + 1) * DM + ch) * LSEQ;
    {
        float2 xv[32];
        #pragma unroll
        for (int r = 0; r < 32; r++) xv[r] = d[jb + 544 * r];
        fft32_inv<9, true>(xv, tid);
        #pragma unroll
        for (int r = 0; r < 16; r++) {
            const int i = tid + (r << 9);
            o0[i] = xv[r].x;
            o1[i] = xv[r].y;
        }
    }
}

// ---------------- launch ----------------------------------------------------
// Input order (metadata): x, z, t, freq, W1, b1, W2, b2, W3, b3, Wout, deltas, D
extern "C" void kernel_launch(void* const* d_in, const int* in_sizes, int n_in,
                              void* d_out, int out_size) {
    (void)in_sizes; (void)n_in; (void)out_size;
    const float* x      = (const float*)d_in[0];
    const float* z      = (const float*)d_in[1];
    const float* t      = (const float*)d_in[2];
    const float* freq   = (const float*)d_in[3];
    const float* W1     = (const float*)d_in[4];
    const float* b1     = (const float*)d_in[5];
    const float* W2     = (const float*)d_in[6];
    const float* b2     = (const float*)d_in[7];
    const float* W3     = (const float*)d_in[8];
    const float* b3     = (const float*)d_in[9];
    const float* Wout   = (const float*)d_in[10];
    const float* deltas = (const float*)d_in[11];
    const float* Dbias  = (const float*)d_in[12];
    float* out = (float*)d_out;

    cudaFuncSetAttribute(kf_kernel,   cudaFuncAttributeMaxDynamicSharedMemorySize, SMEM_BYTES);
    cudaFuncSetAttribute(conv_kernel, cudaFuncAttributeMaxDynamicSharedMemorySize, SMEM_BYTES);

    mlp_kernel<<<LSEQ / 4, 256>>>(z, freq, W1, b1, W2, b2, W3, b3);
    filt_kernel<<<dim3(LSEQ / 32, DM / 128), 256>>>(Wout, t, deltas);
    kf_kernel<<<DM, NT, SMEM_BYTES>>>(Dbias);
    conv_kernel<<<dim3(2, DM), NT, SMEM_BYTES>>>(x, out);
}

// round 14
// speedup vs baseline: 1.0402x; 1.0082x over previous
#include <cuda_runtime.h>
#include <math.h>

// Problem constants
#define LSEQ 8192
#define NFFT 16384          // 2*LSEQ = 32*32*16
#define DM   768
#define EMB  33
#define FO   64
#define SHIFT_C 0.05f
#define NT   512            // FFT threads per CTA

// Pad 1 float2 per 16: PHYS(i) = i + (i>>4).  (verified conflict-free R5)
#define DPAD 17408
#define SMEM_BYTES (DPAD * (int)sizeof(float2))          // 139264 B

// ---------------- scratch (device globals: no allocations allowed) ----------
__device__ float g_S[LSEQ * FO];                         // post-MLP activations
__device__ float g_k[DM * LSEQ];                         // filter k[d][l]
__device__ __align__(16) float2 g_Kf[(size_t)DM * NFFT]; // (spectrum + D)/N, scrambled

// cos / (-sin) of 2*pi*k/32 as compile-time constants -> immediate-form FFMA
__device__ static constexpr float CS32[32] = {
    1.0f,                   0.98078528040323044f,  0.92387953251128674f,  0.83146961230254524f,
    0.70710678118654752f,   0.55557023301960222f,  0.38268343236508977f,  0.19509032201612827f,
    0.0f,                  -0.19509032201612827f, -0.38268343236508977f, -0.55557023301960222f,
   -0.70710678118654752f,  -0.83146961230254524f, -0.92387953251128674f, -0.98078528040323044f,
   -1.0f,                  -0.98078528040323044f, -0.92387953251128674f, -0.83146961230254524f,
   -0.70710678118654752f,  -0.55557023301960222f, -0.38268343236508977f, -0.19509032201612827f,
    0.0f,                   0.19509032201612827f,  0.38268343236508977f,  0.55557023301960222f,
    0.70710678118654752f,   0.83146961230254524f,  0.92387953251128674f,  0.98078528040323044f
};
__device__ static constexpr float SN32[32] = {     // = sin(-2*pi*k/32)
    0.0f,                  -0.19509032201612827f, -0.38268343236508977f, -0.55557023301960222f,
   -0.70710678118654752f,  -0.83146961230254524f, -0.92387953251128674f, -0.98078528040323044f,
   -1.0f,                  -0.98078528040323044f, -0.92387953251128674f, -0.83146961230254524f,
   -0.70710678118654752f,  -0.55557023301960222f, -0.38268343236508977f, -0.19509032201612827f,
    0.0f,                   0.19509032201612827f,  0.38268343236508977f,  0.55557023301960222f,
    0.70710678118654752f,   0.83146961230254524f,  0.92387953251128674f,  0.98078528040323044f,
    1.0f,                   0.98078528040323044f,  0.92387953251128674f,  0.83146961230254524f,
    0.70710678118654752f,   0.55557023301960222f,  0.38268343236508977f,  0.19509032201612827f
};

// ---------------- complex helpers ----------------
__device__ __forceinline__ float2 cadd(float2 a, float2 b){ return make_float2(a.x+b.x, a.y+b.y); }
__device__ __forceinline__ float2 csub(float2 a, float2 b){ return make_float2(a.x-b.x, a.y-b.y); }
__device__ __forceinline__ float2 cmul(float2 a, float2 b){
    return make_float2(a.x*b.x - a.y*b.y, a.x*b.y + a.y*b.x);
}
// multiply by compile-time literal (wx, wy): 2 FMUL-imm + 2 FFMA-imm (rt=1)
__device__ __forceinline__ float2 cmuli(float2 a, float wx, float wy) {
    return make_float2(fmaf(a.y, -wy, a.x * wx), fmaf(a.y, wx, a.x * wy));
}
// a * e^{-2*pi*i*k/32}; k folded to constant under #pragma unroll
__device__ __forceinline__ float2 twf(float2 a, int k) {
    k &= 31;
    if (k == 0)  return a;
    if (k == 8)  return make_float2(a.y, -a.x);     // * -i
    if (k == 16) return make_float2(-a.x, -a.y);    // * -1
    if (k == 24) return make_float2(-a.y, a.x);     // * +i
    return cmuli(a, CS32[k], SN32[k]);
}
// a * e^{+2*pi*i*k/32}
__device__ __forceinline__ float2 twb(float2 a, int k) {
    k &= 31;
    if (k == 0)  return a;
    if (k == 8)  return make_float2(-a.y, a.x);     // * +i
    if (k == 16) return make_float2(-a.x, -a.y);    // * -1
    if (k == 24) return make_float2(a.y, -a.x);     // * -i
    return cmuli(a, CS32[k], -SN32[k]);
}

// radix-4 DIF forward core (no twiddle)
__device__ __forceinline__ void bf4f(float2 x0, float2 x1, float2 x2, float2 x3,
                                     float2& a0, float2& a1, float2& a2, float2& a3) {
    float2 t0 = cadd(x0, x2), t1 = csub(x0, x2);
    float2 t2 = cadd(x1, x3), t3 = csub(x1, x3);
    float2 mi = make_float2(t3.y, -t3.x);                // -i * t3
    a0 = cadd(t0, t2);
    a1 = cadd(t1, mi);
    a2 = csub(t0, t2);
    a3 = csub(t1, mi);
}
// radix-4 inverse core (unscaled)
__device__ __forceinline__ void bf4i(float2 x0, float2 x1, float2 x2, float2 x3,
                                     float2& a0, float2& a1, float2& a2, float2& a3) {
    float2 t0 = cadd(x0, x2), t1 = csub(x0, x2);
    float2 t2 = cadd(x1, x3), t3 = csub(x1, x3);
    float2 pi = make_float2(-t3.y, t3.x);                // +i * t3
    a0 = cadd(t0, t2);
    a1 = cadd(t1, pi);
    a2 = csub(t0, t2);
    a3 = csub(t1, pi);
}

// ---------------- register radix-32 (4*4*2 DIF), external span S = 1<<LS ----
// Twiddles: w_m = b^m * e^{-2*pi*i*m*c/32}; b powers hoisted, rotations literal.
// HALF: x[16..31] implicitly zero on entry.
template<int LS, bool HALF>
__device__ __forceinline__ void fft32_fwd(float2* x, int j) {
    const float C = -6.2831853071795864769f / (float)(1 << (LS + 5));
    float sb, cb;
    __sincosf(C * (float)j, &sb, &cb);
    const float2 b  = make_float2(cb, sb);
    const float2 b2 = cmul(b, b);
    const float2 b3 = cmul(b2, b);
    // stage A: span 8
    #pragma unroll
    for (int c = 0; c < 8; c++) {
        float2 w1 = twf(b,  c);
        float2 w2 = twf(b2, 2 * c);
        float2 w3 = twf(b3, 3 * c);
        float2 a0, a1, a2, a3;
        if (HALF) {
            float2 x0 = x[c], x1 = x[c + 8];
            a0 = cadd(x0, x1);
            a1 = make_float2(x0.x + x1.y, x0.y - x1.x);  // x0 - i*x1
            a2 = csub(x0, x1);
            a3 = make_float2(x0.x - x1.y, x0.y + x1.x);  // x0 + i*x1
        } else {
            bf4f(x[c], x[c+8], x[c+16], x[c+24], a0, a1, a2, a3);
        }
        x[c]      = a0;
        x[c + 8]  = cmul(a1, w1);
        x[c + 16] = cmul(a2, w2);
        x[c + 24] = cmul(a3, w3);
    }
    const float2 b4  = cmul(b2, b2);
    const float2 b8  = cmul(b4, b4);
    const float2 b12 = cmul(b8, b4);
    const float2 b16 = cmul(b8, b8);
    // stage B: span 2; twiddles b4^m * e^{-2*pi*i*4*m*c2/32}
    float2 W1[2], W2[2], W3[2];
    W1[0] = b4;  W2[0] = b8;  W3[0] = b12;
    W1[1] = twf(b4, 4);  W2[1] = twf(b8, 8);  W3[1] = twf(b12, 12);
    #pragma unroll
    for (int g = 0; g < 4; g++) {
        #pragma unroll
        for (int c2 = 0; c2 < 2; c2++) {
            const int i = 8 * g + c2;
            float2 a0, a1, a2, a3;
            bf4f(x[i], x[i+2], x[i+4], x[i+6], a0, a1, a2, a3);
            x[i]     = a0;
            x[i + 2] = cmul(a1, W1[c2]);
            x[i + 4] = cmul(a2, W2[c2]);
            x[i + 6] = cmul(a3, W3[c2]);
        }
    }
    // stage C: radix-2, span 1
    #pragma unroll
    for (int m = 0; m < 16; m++) {
        float2 x0 = x[2*m], x1 = x[2*m + 1];
        x[2*m]     = cadd(x0, x1);
        x[2*m + 1] = cmul(csub(x0, x1), b16);
    }
}

// Inverse (unscaled, gain 32).  HALFOUT: only outputs r<16 are produced.
template<int LS, bool HALFOUT>
__device__ __forceinline__ void fft32_inv(float2* x, int j) {
    const float C = -6.2831853071795864769f / (float)(1 << (LS + 5));
    float sb, cb;
    __sincosf(C * (float)j, &sb, &cb);
    const float2 b   = make_float2(cb, -sb);             // conj base
    const float2 b2  = cmul(b, b);
    const float2 b3  = cmul(b2, b);
    const float2 b4  = cmul(b2, b2);
    const float2 b8  = cmul(b4, b4);
    const float2 b12 = cmul(b8, b4);
    const float2 b16 = cmul(b8, b8);
    // stage C'
    #pragma unroll
    for (int m = 0; m < 16; m++) {
        float2 z1 = cmul(x[2*m + 1], b16);
        float2 x0 = x[2*m];
        x[2*m]     = cadd(x0, z1);
        x[2*m + 1] = csub(x0, z1);
    }
    // stage B'
    float2 W1[2], W2[2], W3[2];
    W1[0] = b4;  W2[0] = b8;  W3[0] = b12;
    W1[1] = twb(b4, 4);  W2[1] = twb(b8, 8);  W3[1] = twb(b12, 12);
    #pragma unroll
    for (int g = 0; g < 4; g++) {
        #pragma unroll
        for (int c2 = 0; c2 < 2; c2++) {
            const int i = 8 * g + c2;
            float2 z0 = x[i];
            float2 z1 = cmul(x[i + 2], W1[c2]);
            float2 z2 = cmul(x[i + 4], W2[c2]);
            float2 z3 = cmul(x[i + 6], W3[c2]);
            bf4i(z0, z1, z2, z3, x[i], x[i+2], x[i+4], x[i+6]);
        }
    }
    // stage A'
    #pragma unroll
    for (int c = 0; c < 8; c++) {
        float2 w1 = twb(b,  c);
        float2 w2 = twb(b2, 2 * c);
        float2 w3 = twb(b3, 3 * c);
        float2 z0 = x[c];
        float2 z1 = cmul(x[c + 8],  w1);
        float2 z2 = cmul(x[c + 16], w2);
        float2 z3 = cmul(x[c + 24], w3);
        if (HALFOUT) {
            float2 t0 = cadd(z0, z2), t1 = csub(z0, z2);
            float2 t2 = cadd(z1, z3), t3 = csub(z1, z3);
            float2 pi = make_float2(-t3.y, t3.x);
            x[c]     = cadd(t0, t2);
            x[c + 8] = cadd(t1, pi);
        } else {
            bf4i(z0, z1, z2, z3, x[c], x[c+8], x[c+16], x[c+24]);
        }
    }
}

// ---------------- 16-point cores: ALL twiddles literal ----------------------
__device__ __forceinline__ void fft16c_fwd(float2* x) {
    #pragma unroll
    for (int c = 0; c < 4; c++) {
        float2 a0, a1, a2, a3;
        bf4f(x[c], x[c+4], x[c+8], x[c+12], a0, a1, a2, a3);
        x[c]      = a0;
        x[c + 4]  = twf(a1, 2 * c);
        x[c + 8]  = twf(a2, 4 * c);
        x[c + 12] = twf(a3, 6 * c);
    }
    #pragma unroll
    for (int m = 0; m < 4; m++) {
        float2 a0, a1, a2, a3;
        bf4f(x[4*m], x[4*m+1], x[4*m+2], x[4*m+3], a0, a1, a2, a3);
        x[4*m] = a0; x[4*m+1] = a1; x[4*m+2] = a2; x[4*m+3] = a3;
    }
}
__device__ __forceinline__ void fft16c_inv(float2* x) {
    #pragma unroll
    for (int m = 0; m < 4; m++) {
        float2 a0, a1, a2, a3;
        bf4i(x[4*m], x[4*m+1], x[4*m+2], x[4*m+3], a0, a1, a2, a3);
        x[4*m] = a0; x[4*m+1] = a1; x[4*m+2] = a2; x[4*m+3] = a3;
    }
    #pragma unroll
    for (int c = 0; c < 4; c++) {
        float2 z1 = twb(x[c + 4],  2 * c);
        float2 z2 = twb(x[c + 8],  4 * c);
        float2 z3 = twb(x[c + 12], 6 * c);
        bf4i(x[c], z1, z2, z3, x[c], x[c+4], x[c+8], x[c+12]);
    }
}

// ---------------- filter MLP stages 1-3 (fast-intrinsic sin) -----------------
__global__ void mlp_kernel(const float* __restrict__ z, const float* __restrict__ freq,
                           const float* __restrict__ W1, const float* __restrict__ b1,
                           const float* __restrict__ W2, const float* __restrict__ b2,
                           const float* __restrict__ W3, const float* __restrict__ b3) {
    __shared__ float zs[4][EMB];
    __shared__ float as[4][FO];
    __shared__ float bs[4][FO];
    const int tid = threadIdx.x;
    const int lg  = tid >> 6;
    const int f   = tid & 63;
    const int l   = blockIdx.x * 4 + lg;

    if (f < EMB) zs[lg][f] = z[l * EMB + f];
    __syncthreads();

    const float fr = freq[f];

    float acc = b1[f];
    #pragma unroll
    for (int e = 0; e < EMB; e++) acc += zs[lg][e] * W1[e * FO + f];
    as[lg][f] = __sinf(fr * acc);
    __syncthreads();

    acc = b2[f];
    #pragma unroll
    for (int e = 0; e < FO; e++) acc += as[lg][e] * W2[e * FO + f];
    bs[lg][f] = __sinf(fr * acc);
    __syncthreads();

    acc = b3[f];
    #pragma unroll
    for (int e = 0; e < FO; e++) acc += bs[lg][e] * W3[e * FO + f];
    g_S[l * FO + f] = __sinf(fr * acc);
}

// ---------------- output projection + exponential modulation ----------------
// expf(-t_l * a) is geometric in l (t = linspace step 1/8191):
// 2 exp per thread instead of 16.
__global__ void filt_kernel(const float* __restrict__ Wout, const float* __restrict__ t,
                            const float* __restrict__ deltas) {
    __shared__ float Ss[32][FO];
    __shared__ float Ws[FO][128];
    const int tid = threadIdx.x;
    const int l0  = blockIdx.x * 32;
    const int d0  = blockIdx.y * 128;

    for (int i = tid; i < 32 * FO; i += 256)
        Ss[i >> 6][i & 63] = g_S[(l0 + (i >> 6)) * FO + (i & 63)];
    for (int i = tid; i < FO * 128; i += 256)
        Ws[i >> 7][i & 127] = Wout[(i >> 7) * DM + d0 + (i & 127)];
    __syncthreads();

    const int dl  = tid & 127;
    const int lgp = tid >> 7;
    float acc[16];
    #pragma unroll
    for (int i = 0; i < 16; i++) acc[i] = 0.0f;
    #pragma unroll
    for (int f = 0; f < FO; f++) {
        const float w = Ws[f][dl];
        #pragma unroll
        for (int i = 0; i < 16; i++) acc[i] += Ss[lgp * 16 + i][f] * w;
    }
    const int d = d0 + dl;
    const float ad = fabsf(deltas[d]);
    const int lbase = l0 + lgp * 16;
    float e = __expf(-t[lbase] * ad);
    const float rr = __expf(-ad * (1.0f / 8191.0f));
    float* kout = g_k + (size_t)d * LSEQ + lbase;
    #pragma unroll
    for (int i = 0; i < 16; i++) {
        kout[i] = acc[i] * (e + SHIFT_C);
        e *= rr;
    }
}

// ---------------- kernel spectrum (+D baked in), per-channel ----------------
__global__ void __launch_bounds__(NT, 1)
kf_kernel(const float* __restrict__ Dbias) {
    extern __shared__ float2 d[];
    const int tid = threadIdx.x;
    const int ch  = blockIdx.x;

    const float* krow = g_k + (size_t)ch * LSEQ;
    const int jb = tid + (tid >> 4);                     // PHYS(tid)

    // P1: radix-32, S=512; top half zero
    {
        float2 xv[32];
        #pragma unroll
        for (int r = 0; r < 16; r++)
            xv[r] = make_float2(krow[tid + (r << 9)], 0.0f);
        fft32_fwd<9, true>(xv, tid);
        #pragma unroll
        for (int r = 0; r < 32; r++) d[jb + 544 * r] = xv[r];
    }
    __syncthreads();

    const int j2 = tid & 15;
    const int b0 = (tid >> 4) * 544 + j2;

    // P2: radix-32, S=16
    {
        float2 xv[32];
        #pragma unroll
        for (int r = 0; r < 32; r++) xv[r] = d[b0 + 17 * r];
        fft32_fwd<4, false>(xv, j2);
        #pragma unroll
        for (int r = 0; r < 32; r++) d[b0 + 17 * r] = xv[r];
    }
    __syncthreads();

    // P3: const-twiddle fwd16 + bake (spec + D)/N, store to g_Kf
    float2* outp = g_Kf + (size_t)ch * NFFT;
    const float sc = 1.0f / (float)NFFT;
    const float Dd = Dbias[ch];
    #pragma unroll
    for (int k = 0; k < 2; k++) {
        const int q  = tid + k * NT;
        const int pb = 17 * q;                           // PHYS(16q)
        float2 xv[16];
        #pragma unroll
        for (int r = 0; r < 16; r++) xv[r] = d[pb + r];
        fft16c_fwd(xv);
        float4* o4 = reinterpret_cast<float4*>(outp + 16 * q);
        #pragma unroll
        for (int i = 0; i < 8; i++) {
            o4[i] = make_float4((xv[2*i].x + Dd) * sc, xv[2*i].y * sc,
                                (xv[2*i+1].x + Dd) * sc, xv[2*i+1].y * sc);
        }
    }
}

// ---------------- conv ------------------------------------------------------
// grid = dim3(2, DM): the two batch-pair CTAs of a channel are adjacent in
// linear block order -> co-resident -> second Kf read hits L2.
__global__ void __launch_bounds__(NT, 1)
conv_kernel(const float* __restrict__ x, float* __restrict__ out) {
    extern __shared__ float2 d[];
    const int tid = threadIdx.x;
    const int ch  = blockIdx.y;
    const int p   = blockIdx.x;                          // batch pair

    const float* u0 = x + ((size_t)(2*p)     * DM + ch) * LSEQ;
    const float* u1 = x + ((size_t)(2*p + 1) * DM + ch) * LSEQ;
    const float2* kf = g_Kf + (size_t)ch * NFFT;

    // prefetch this thread's Kf lines into L2 (consumed in P3, ~2500 cyc away)
    asm volatile("prefetch.global.L2 [%0];" :: "l"(kf + 16 * tid));
    asm volatile("prefetch.global.L2 [%0];" :: "l"(kf + 16 * (tid + NT)));

    const int jb = tid + (tid >> 4);

    // P1 fwd: radix-32, S=512; pack u0 + i*u1; top half zero
    {
        float2 xv[32];
        #pragma unroll
        for (int r = 0; r < 16; r++) {
            const int i = tid + (r << 9);
            xv[r] = make_float2(u0[i], u1[i]);
        }
        fft32_fwd<9, true>(xv, tid);
        #pragma unroll
        for (int r = 0; r < 32; r++) d[jb + 544 * r] = xv[r];
    }
    __syncthreads();

    const int j2 = tid & 15;
    const int b0 = (tid >> 4) * 544 + j2;

    // P2 fwd: radix-32, S=16
    {
        float2 xv[32];
        #pragma unroll
        for (int r = 0; r < 32; r++) xv[r] = d[b0 + 17 * r];
        fft32_fwd<4, false>(xv, j2);
        #pragma unroll
        for (int r = 0; r < 32; r++) d[b0 + 17 * r] = xv[r];
    }
    __syncthreads();

    // P3: const-twiddle fwd16 -> * Kf (D baked in) -> const-twiddle inv16
    #pragma unroll
    for (int k = 0; k < 2; k++) {
        const int q  = tid + k * NT;
        const int pb = 17 * q;
        float4 kreg[8];
        const float4* kf4 = reinterpret_cast<const float4*>(kf + 16 * q);
        #pragma unroll
        for (int i = 0; i < 8; i++) kreg[i] = kf4[i];    // prefetch over fwd16
        float2 xv[16];
        #pragma unroll
        for (int r = 0; r < 16; r++) xv[r] = d[pb + r];
        fft16c_fwd(xv);
        #pragma unroll
        for (int i = 0; i < 8; i++) {
            xv[2*i]   = cmul(xv[2*i],   make_float2(kreg[i].x, kreg[i].y));
            xv[2*i+1] = cmul(xv[2*i+1], make_float2(kreg[i].z, kreg[i].w));
        }
        fft16c_inv(xv);
        #pragma unroll
        for (int r = 0; r < 16; r++) d[pb + r] = xv[r];
    }
    __syncthreads();

    // P2' inv
    {
        float2 xv[32];
        #pragma unroll
        for (int r = 0; r < 32; r++) xv[r] = d[b0 + 17 * r];
        fft32_inv<4, false>(xv, j2);
        #pragma unroll
        for (int r = 0; r < 32; r++) d[b0 + 17 * r] = xv[r];
    }
    __syncthreads();

    // P1' inv: half output, direct global store
    float* o0 = out + ((size_t)(2*p)     * DM + ch) * LSEQ;
    float* o1 = out + ((size_t)(2*p + 1) * DM + ch) * LSEQ;
    {
        float2 xv[32];
        #pragma unroll
        for (int r = 0; r < 32; r++) xv[r] = d[jb + 544 * r];
        fft32_inv<9, true>(xv, tid);
        #pragma unroll
        for (int r = 0; r < 16; r++) {
            const int i = tid + (r << 9);
            o0[i] = xv[r].x;
            o1[i] = xv[r].y;
        }
    }
}

// ---------------- launch ----------------------------------------------------
// Input order (metadata): x, z, t, freq, W1, b1, W2, b2, W3, b3, Wout, deltas, D
extern "C" void kernel_launch(void* const* d_in, const int* in_sizes, int n_in,
                              void* d_out, int out_size) {
    (void)in_sizes; (void)n_in; (void)out_size;
    const float* x      = (const float*)d_in[0];
    const float* z      = (const float*)d_in[1];
    const float* t      = (const float*)d_in[2];
    const float* freq   = (const float*)d_in[3];
    const float* W1     = (const float*)d_in[4];
    const float* b1     = (const float*)d_in[5];
    const float* W2     = (const float*)d_in[6];
    const float* b2     = (const float*)d_in[7];
    const float* W3     = (const float*)d_in[8];
    const float* b3     = (const float*)d_in[9];
    const float* Wout   = (const float*)d_in[10];
    const float* deltas = (const float*)d_in[11];
    const float* Dbias  = (const float*)d_in[12];
    float* out = (float*)d_out;

    cudaFuncSetAttribute(kf_kernel,   cudaFuncAttributeMaxDynamicSharedMemorySize, SMEM_BYTES);
    cudaFuncSetAttribute(conv_kernel, cudaFuncAttributeMaxDynamicSharedMemorySize, SMEM_BYTES);

    mlp_kernel<<<LSEQ / 4, 256>>>(z, freq, W1, b1, W2, b2, W3, b3);
    filt_kernel<<<dim3(LSEQ / 32, DM / 128), 256>>>(Wout, t, deltas);
    kf_kernel<<<DM, NT, SMEM_BYTES>>>(Dbias);
    conv_kernel<<<dim3(2, DM), NT, SMEM_BYTES>>>(x, out);
}

// round 15
// speedup vs baseline: 1.1084x; 1.0655x over previous
#include <cuda_runtime.h>
#include <math.h>

// Problem constants
#define LSEQ 8192
#define NFFT 16384          // 2*LSEQ = 32*32*16
#define DM   768
#define EMB  33
#define FO   64
#define SHIFT_C 0.05f
#define NT   512            // FFT threads per CTA

// Pad 1 float2 per 16: PHYS(i) = i + (i>>4).  (verified conflict-free R5)
#define DPAD 17408
#define SMEM_BYTES (DPAD * (int)sizeof(float2))          // 139264 B

// ---------------- scratch (device globals: no allocations allowed) ----------
__device__ float g_S[LSEQ * FO];                         // post-MLP activations
__device__ float g_k[DM * LSEQ];                         // filter k[d][l]
__device__ __align__(16) float2 g_Kf[(size_t)DM * NFFT]; // (spectrum + D)/N, scrambled,
                                                         // ONLY canonical blocks valid

// cos / (-sin) of 2*pi*k/32 as compile-time constants -> immediate-form FFMA
__device__ static constexpr float CS32[32] = {
    1.0f,                   0.98078528040323044f,  0.92387953251128674f,  0.83146961230254524f,
    0.70710678118654752f,   0.55557023301960222f,  0.38268343236508977f,  0.19509032201612827f,
    0.0f,                  -0.19509032201612827f, -0.38268343236508977f, -0.55557023301960222f,
   -0.70710678118654752f,  -0.83146961230254524f, -0.92387953251128674f, -0.98078528040323044f,
   -1.0f,                  -0.98078528040323044f, -0.92387953251128674f, -0.83146961230254524f,
   -0.70710678118654752f,  -0.55557023301960222f, -0.38268343236508977f, -0.19509032201612827f,
    0.0f,                   0.19509032201612827f,  0.38268343236508977f,  0.55557023301960222f,
    0.70710678118654752f,   0.83146961230254524f,  0.92387953251128674f,  0.98078528040323044f
};
__device__ static constexpr float SN32[32] = {     // = sin(-2*pi*k/32)
    0.0f,                  -0.19509032201612827f, -0.38268343236508977f, -0.55557023301960222f,
   -0.70710678118654752f,  -0.83146961230254524f, -0.92387953251128674f, -0.98078528040323044f,
   -1.0f,                  -0.98078528040323044f, -0.92387953251128674f, -0.83146961230254524f,
   -0.70710678118654752f,  -0.55557023301960222f, -0.38268343236508977f, -0.19509032201612827f,
    0.0f,                   0.19509032201612827f,  0.38268343236508977f,  0.55557023301960222f,
    0.70710678118654752f,   0.83146961230254524f,  0.92387953251128674f,  0.98078528040323044f,
    1.0f,                   0.98078528040323044f,  0.92387953251128674f,  0.83146961230254524f,
    0.70710678118654752f,   0.55557023301960222f,  0.38268343236508977f,  0.19509032201612827f
};

// ---------------- complex helpers ----------------
__device__ __forceinline__ float2 cadd(float2 a, float2 b){ return make_float2(a.x+b.x, a.y+b.y); }
__device__ __forceinline__ float2 csub(float2 a, float2 b){ return make_float2(a.x-b.x, a.y-b.y); }
__device__ __forceinline__ float2 cmul(float2 a, float2 b){
    return make_float2(a.x*b.x - a.y*b.y, a.x*b.y + a.y*b.x);
}
// multiply by compile-time literal (wx, wy): 2 FMUL-imm + 2 FFMA-imm (rt=1)
__device__ __forceinline__ float2 cmuli(float2 a, float wx, float wy) {
    return make_float2(fmaf(a.y, -wy, a.x * wx), fmaf(a.y, wx, a.x * wy));
}
// a * e^{-2*pi*i*k/32}; k folded to constant under #pragma unroll
__device__ __forceinline__ float2 twf(float2 a, int k) {
    k &= 31;
    if (k == 0)  return a;
    if (k == 8)  return make_float2(a.y, -a.x);     // * -i
    if (k == 16) return make_float2(-a.x, -a.y);    // * -1
    if (k == 24) return make_float2(-a.y, a.x);     // * +i
    return cmuli(a, CS32[k], SN32[k]);
}
// a * e^{+2*pi*i*k/32}
__device__ __forceinline__ float2 twb(float2 a, int k) {
    k &= 31;
    if (k == 0)  return a;
    if (k == 8)  return make_float2(-a.y, a.x);     // * +i
    if (k == 16) return make_float2(-a.x, -a.y);    // * -1
    if (k == 24) return make_float2(a.y, -a.x);     // * -i
    return cmuli(a, CS32[k], -SN32[k]);
}

// radix-4 DIF forward core (no twiddle)
__device__ __forceinline__ void bf4f(float2 x0, float2 x1, float2 x2, float2 x3,
                                     float2& a0, float2& a1, float2& a2, float2& a3) {
    float2 t0 = cadd(x0, x2), t1 = csub(x0, x2);
    float2 t2 = cadd(x1, x3), t3 = csub(x1, x3);
    float2 mi = make_float2(t3.y, -t3.x);                // -i * t3
    a0 = cadd(t0, t2);
    a1 = cadd(t1, mi);
    a2 = csub(t0, t2);
    a3 = csub(t1, mi);
}
// radix-4 inverse core (unscaled)
__device__ __forceinline__ void bf4i(float2 x0, float2 x1, float2 x2, float2 x3,
                                     float2& a0, float2& a1, float2& a2, float2& a3) {
    float2 t0 = cadd(x0, x2), t1 = csub(x0, x2);
    float2 t2 = cadd(x1, x3), t3 = csub(x1, x3);
    float2 pi = make_float2(-t3.y, t3.x);                // +i * t3
    a0 = cadd(t0, t2);
    a1 = cadd(t1, pi);
    a2 = csub(t0, t2);
    a3 = csub(t1, pi);
}

// ---------------- register radix-32 (4*4*2 DIF), external span S = 1<<LS ----
// Twiddles: w_m = b^m * e^{-2*pi*i*m*c/32}; b powers hoisted, rotations literal.
// HALF: x[16..31] implicitly zero on entry.
template<int LS, bool HALF>
__device__ __forceinline__ void fft32_fwd(float2* x, int j) {
    const float C = -6.2831853071795864769f / (float)(1 << (LS + 5));
    float sb, cb;
    __sincosf(C * (float)j, &sb, &cb);
    const float2 b  = make_float2(cb, sb);
    const float2 b2 = cmul(b, b);
    const float2 b3 = cmul(b2, b);
    // stage A: span 8
    #pragma unroll
    for (int c = 0; c < 8; c++) {
        float2 w1 = twf(b,  c);
        float2 w2 = twf(b2, 2 * c);
        float2 w3 = twf(b3, 3 * c);
        float2 a0, a1, a2, a3;
        if (HALF) {
            float2 x0 = x[c], x1 = x[c + 8];
            a0 = cadd(x0, x1);
            a1 = make_float2(x0.x + x1.y, x0.y - x1.x);  // x0 - i*x1
            a2 = csub(x0, x1);
            a3 = make_float2(x0.x - x1.y, x0.y + x1.x);  // x0 + i*x1
        } else {
            bf4f(x[c], x[c+8], x[c+16], x[c+24], a0, a1, a2, a3);
        }
        x[c]      = a0;
        x[c + 8]  = cmul(a1, w1);
        x[c + 16] = cmul(a2, w2);
        x[c + 24] = cmul(a3, w3);
    }
    const float2 b4  = cmul(b2, b2);
    const float2 b8  = cmul(b4, b4);
    const float2 b12 = cmul(b8, b4);
    const float2 b16 = cmul(b8, b8);
    // stage B: span 2; twiddles b4^m * e^{-2*pi*i*4*m*c2/32}
    float2 W1[2], W2[2], W3[2];
    W1[0] = b4;  W2[0] = b8;  W3[0] = b12;
    W1[1] = twf(b4, 4);  W2[1] = twf(b8, 8);  W3[1] = twf(b12, 12);
    #pragma unroll
    for (int g = 0; g < 4; g++) {
        #pragma unroll
        for (int c2 = 0; c2 < 2; c2++) {
            const int i = 8 * g + c2;
            float2 a0, a1, a2, a3;
            bf4f(x[i], x[i+2], x[i+4], x[i+6], a0, a1, a2, a3);
            x[i]     = a0;
            x[i + 2] = cmul(a1, W1[c2]);
            x[i + 4] = cmul(a2, W2[c2]);
            x[i + 6] = cmul(a3, W3[c2]);
        }
    }
    // stage C: radix-2, span 1
    #pragma unroll
    for (int m = 0; m < 16; m++) {
        float2 x0 = x[2*m], x1 = x[2*m + 1];
        x[2*m]     = cadd(x0, x1);
        x[2*m + 1] = cmul(csub(x0, x1), b16);
    }
}

// Inverse (unscaled, gain 32).  HALFOUT: only outputs r<16 are produced.
template<int LS, bool HALFOUT>
__device__ __forceinline__ void fft32_inv(float2* x, int j) {
    const float C = -6.2831853071795864769f / (float)(1 << (LS + 5));
    float sb, cb;
    __sincosf(C * (float)j, &sb, &cb);
    const float2 b   = make_float2(cb, -sb);             // conj base
    const float2 b2  = cmul(b, b);
    const float2 b3  = cmul(b2, b);
    const float2 b4  = cmul(b2, b2);
    const float2 b8  = cmul(b4, b4);
    const float2 b12 = cmul(b8, b4);
    const float2 b16 = cmul(b8, b8);
    // stage C'
    #pragma unroll
    for (int m = 0; m < 16; m++) {
        float2 z1 = cmul(x[2*m + 1], b16);
        float2 x0 = x[2*m];
        x[2*m]     = cadd(x0, z1);
        x[2*m + 1] = csub(x0, z1);
    }
    // stage B'
    float2 W1[2], W2[2], W3[2];
    W1[0] = b4;  W2[0] = b8;  W3[0] = b12;
    W1[1] = twb(b4, 4);  W2[1] = twb(b8, 8);  W3[1] = twb(b12, 12);
    #pragma unroll
    for (int g = 0; g < 4; g++) {
        #pragma unroll
        for (int c2 = 0; c2 < 2; c2++) {
            const int i = 8 * g + c2;
            float2 z0 = x[i];
            float2 z1 = cmul(x[i + 2], W1[c2]);
            float2 z2 = cmul(x[i + 4], W2[c2]);
            float2 z3 = cmul(x[i + 6], W3[c2]);
            bf4i(z0, z1, z2, z3, x[i], x[i+2], x[i+4], x[i+6]);
        }
    }
    // stage A'
    #pragma unroll
    for (int c = 0; c < 8; c++) {
        float2 w1 = twb(b,  c);
        float2 w2 = twb(b2, 2 * c);
        float2 w3 = twb(b3, 3 * c);
        float2 z0 = x[c];
        float2 z1 = cmul(x[c + 8],  w1);
        float2 z2 = cmul(x[c + 16], w2);
        float2 z3 = cmul(x[c + 24], w3);
        if (HALFOUT) {
            float2 t0 = cadd(z0, z2), t1 = csub(z0, z2);
            float2 t2 = cadd(z1, z3), t3 = csub(z1, z3);
            float2 pi = make_float2(-t3.y, t3.x);
            x[c]     = cadd(t0, t2);
            x[c + 8] = cadd(t1, pi);
        } else {
            bf4i(z0, z1, z2, z3, x[c], x[c+8], x[c+16], x[c+24]);
        }
    }
}

// ---------------- 16-point cores: ALL twiddles literal ----------------------
__device__ __forceinline__ void fft16c_fwd(float2* x) {
    #pragma unroll
    for (int c = 0; c < 4; c++) {
        float2 a0, a1, a2, a3;
        bf4f(x[c], x[c+4], x[c+8], x[c+12], a0, a1, a2, a3);
        x[c]      = a0;
        x[c + 4]  = twf(a1, 2 * c);
        x[c + 8]  = twf(a2, 4 * c);
        x[c + 12] = twf(a3, 6 * c);
    }
    #pragma unroll
    for (int m = 0; m < 4; m++) {
        float2 a0, a1, a2, a3;
        bf4f(x[4*m], x[4*m+1], x[4*m+2], x[4*m+3], a0, a1, a2, a3);
        x[4*m] = a0; x[4*m+1] = a1; x[4*m+2] = a2; x[4*m+3] = a3;
    }
}
__device__ __forceinline__ void fft16c_inv(float2* x) {
    #pragma unroll
    for (int m = 0; m < 4; m++) {
        float2 a0, a1, a2, a3;
        bf4i(x[4*m], x[4*m+1], x[4*m+2], x[4*m+3], a0, a1, a2, a3);
        x[4*m] = a0; x[4*m+1] = a1; x[4*m+2] = a2; x[4*m+3] = a3;
    }
    #pragma unroll
    for (int c = 0; c < 4; c++) {
        float2 z1 = twb(x[c + 4],  2 * c);
        float2 z2 = twb(x[c + 8],  4 * c);
        float2 z3 = twb(x[c + 12], 6 * c);
        bf4i(x[c], z1, z2, z3, x[c], x[c+4], x[c+8], x[c+12]);
    }
}

// Hermitian partner of a scrambled 16-element block index q (R11-verified):
// (+1)-complement through digit reversal for the 32-groups.
__device__ __forceinline__ int prt32(int m) {
    return (m >= 8) ? (39 - m) : ((m >= 2) ? (9 - m) : 1);
}
__device__ __forceinline__ int partner_block(int q) {
    const int m2 = q & 31, m1 = q >> 5;
    if (m1 >= 1) return (31 - m2) + 32 * prt32(m1);
    if (m2 >= 1) return prt32(m2);
    return 0;
}

// ---------------- filter MLP stages 1-3 (fast-intrinsic sin) -----------------
__global__ void mlp_kernel(const float* __restrict__ z, const float* __restrict__ freq,
                           const float* __restrict__ W1, const float* __restrict__ b1,
                           const float* __restrict__ W2, const float* __restrict__ b2,
                           const float* __restrict__ W3, const float* __restrict__ b3) {
    __shared__ float zs[4][EMB];
    __shared__ float as[4][FO];
    __shared__ float bs[4][FO];
    const int tid = threadIdx.x;
    const int lg  = tid >> 6;
    const int f   = tid & 63;
    const int l   = blockIdx.x * 4 + lg;

    if (f < EMB) zs[lg][f] = z[l * EMB + f];
    __syncthreads();

    const float fr = freq[f];

    float acc = b1[f];
    #pragma unroll
    for (int e = 0; e < EMB; e++) acc += zs[lg][e] * W1[e * FO + f];
    as[lg][f] = __sinf(fr * acc);
    __syncthreads();

    acc = b2[f];
    #pragma unroll
    for (int e = 0; e < FO; e++) acc += as[lg][e] * W2[e * FO + f];
    bs[lg][f] = __sinf(fr * acc);
    __syncthreads();

    acc = b3[f];
    #pragma unroll
    for (int e = 0; e < FO; e++) acc += bs[lg][e] * W3[e * FO + f];
    g_S[l * FO + f] = __sinf(fr * acc);
}

// ---------------- output projection + exponential modulation ----------------
__global__ void filt_kernel(const float* __restrict__ Wout, const float* __restrict__ t,
                            const float* __restrict__ deltas) {
    __shared__ float Ss[32][FO];
    __shared__ float Ws[FO][128];
    const int tid = threadIdx.x;
    const int l0  = blockIdx.x * 32;
    const int d0  = blockIdx.y * 128;

    for (int i = tid; i < 32 * FO; i += 256)
        Ss[i >> 6][i & 63] = g_S[(l0 + (i >> 6)) * FO + (i & 63)];
    for (int i = tid; i < FO * 128; i += 256)
        Ws[i >> 7][i & 127] = Wout[(i >> 7) * DM + d0 + (i & 127)];
    __syncthreads();

    const int dl  = tid & 127;
    const int lgp = tid >> 7;
    float acc[16];
    #pragma unroll
    for (int i = 0; i < 16; i++) acc[i] = 0.0f;
    #pragma unroll
    for (int f = 0; f < FO; f++) {
        const float w = Ws[f][dl];
        #pragma unroll
        for (int i = 0; i < 16; i++) acc[i] += Ss[lgp * 16 + i][f] * w;
    }
    const int d = d0 + dl;
    const float ad = fabsf(deltas[d]);
    const int lbase = l0 + lgp * 16;
    float e = __expf(-t[lbase] * ad);
    const float rr = __expf(-ad * (1.0f / 8191.0f));
    float* kout = g_k + (size_t)d * LSEQ + lbase;
    #pragma unroll
    for (int i = 0; i < 16; i++) {
        kout[i] = acc[i] * (e + SHIFT_C);
        e *= rr;
    }
}

// ---------------- kernel spectrum: write CANONICAL blocks only --------------
__global__ void __launch_bounds__(NT, 1)
kf_kernel(const float* __restrict__ Dbias) {
    extern __shared__ float2 d[];
    const int tid = threadIdx.x;
    const int ch  = blockIdx.x;

    const float* krow = g_k + (size_t)ch * LSEQ;
    const int jb = tid + (tid >> 4);                     // PHYS(tid)

    // P1: radix-32, S=512; top half zero
    {
        float2 xv[32];
        #pragma unroll
        for (int r = 0; r < 16; r++)
            xv[r] = make_float2(krow[tid + (r << 9)], 0.0f);
        fft32_fwd<9, true>(xv, tid);
        #pragma unroll
        for (int r = 0; r < 32; r++) d[jb + 544 * r] = xv[r];
    }
    __syncthreads();

    const int j2 = tid & 15;
    const int b0 = (tid >> 4) * 544 + j2;

    // P2: radix-32, S=16
    {
        float2 xv[32];
        #pragma unroll
        for (int r = 0; r < 32; r++) xv[r] = d[b0 + 17 * r];
        fft32_fwd<4, false>(xv, j2);
        #pragma unroll
        for (int r = 0; r < 32; r++) d[b0 + 17 * r] = xv[r];
    }
    __syncthreads();

    // P3: const-twiddle fwd16 + bake (spec + D)/N; store canonical blocks only
    float2* outp = g_Kf + (size_t)ch * NFFT;
    const float sc = 1.0f / (float)NFFT;
    const float Dd = Dbias[ch];
    #pragma unroll
    for (int k = 0; k < 2; k++) {
        const int q  = tid + k * NT;
        const int pb = 17 * q;                           // PHYS(16q)
        float2 xv[16];
        #pragma unroll
        for (int r = 0; r < 16; r++) xv[r] = d[pb + r];
        fft16c_fwd(xv);
        if (q <= partner_block(q)) {                     // canonical
            float4* o4 = reinterpret_cast<float4*>(outp + 16 * q);
            #pragma unroll
            for (int i = 0; i < 8; i++) {
                o4[i] = make_float4((xv[2*i].x + Dd) * sc, xv[2*i].y * sc,
                                    (xv[2*i+1].x + Dd) * sc, xv[2*i+1].y * sc);
            }
        }
    }
}

// ---------------- conv ------------------------------------------------------
// grid = dim3(2, DM): twin CTAs per channel adjacent -> Kf L2 sharing.
// Kf holds only canonical blocks; non-canonical threads reconstruct via
// reversed-conjugate of the partner block (static pattern).
__global__ void __launch_bounds__(NT, 1)
conv_kernel(const float* __restrict__ x, float* __restrict__ out) {
    extern __shared__ float2 d[];
    const int tid = threadIdx.x;
    const int ch  = blockIdx.y;
    const int p   = blockIdx.x;                          // batch pair

    const float* u0 = x + ((size_t)(2*p)     * DM + ch) * LSEQ;
    const float* u1 = x + ((size_t)(2*p + 1) * DM + ch) * LSEQ;
    const float2* kf = g_Kf + (size_t)ch * NFFT;

    // prefetch effective (canonical) Kf lines into L2
    {
        const int qe0 = min(tid, partner_block(tid));
        const int qe1 = min(tid + NT, partner_block(tid + NT));
        asm volatile("prefetch.global.L2 [%0];" :: "l"(kf + 16 * qe0));
        asm volatile("prefetch.global.L2 [%0];" :: "l"(kf + 16 * qe1));
    }

    const int jb = tid + (tid >> 4);

    // P1 fwd: radix-32, S=512; pack u0 + i*u1; top half zero
    {
        float2 xv[32];
        #pragma unroll
        for (int r = 0; r < 16; r++) {
            const int i = tid + (r << 9);
            xv[r] = make_float2(u0[i], u1[i]);
        }
        fft32_fwd<9, true>(xv, tid);
        #pragma unroll
        for (int r = 0; r < 32; r++) d[jb + 544 * r] = xv[r];
    }
    __syncthreads();

    const int j2 = tid & 15;
    const int b0 = (tid >> 4) * 544 + j2;

    // P2 fwd: radix-32, S=16
    {
        float2 xv[32];
        #pragma unroll
        for (int r = 0; r < 32; r++) xv[r] = d[b0 + 17 * r];
        fft32_fwd<4, false>(xv, j2);
        #pragma unroll
        for (int r = 0; r < 32; r++) d[b0 + 17 * r] = xv[r];
    }
    __syncthreads();

    // P3: const-twiddle fwd16 -> * Kf (Hermitian-half) -> const-twiddle inv16
    #pragma unroll
    for (int k = 0; k < 2; k++) {
        const int q  = tid + k * NT;
        const int pb = 17 * q;
        const int qb = partner_block(q);
        const bool canon = (q <= qb);
        const int qe = canon ? q : qb;
        float4 kreg[8];
        const float4* kf4 = reinterpret_cast<const float4*>(kf + 16 * qe);
        #pragma unroll
        for (int i = 0; i < 8; i++) kreg[i] = kf4[i];    // prefetch over fwd16
        float2 xv[16];
        #pragma unroll
        for (int r = 0; r < 16; r++) xv[r] = d[pb + r];
        fft16c_fwd(xv);
        if (canon) {
            #pragma unroll
            for (int i = 0; i < 8; i++) {
                xv[2*i]   = cmul(xv[2*i],   make_float2(kreg[i].x, kreg[i].y));
                xv[2*i+1] = cmul(xv[2*i+1], make_float2(kreg[i].z, kreg[i].w));
            }
        } else {
            // needed[m3] = conj(stored[15 - m3]):
            //   m3=2i   -> conj(kreg[7-i].zw)
            //   m3=2i+1 -> conj(kreg[7-i].xy)
            #pragma unroll
            for (int i = 0; i < 8; i++) {
                xv[2*i]   = cmul(xv[2*i],   make_float2(kreg[7-i].z, -kreg[7-i].w));
                xv[2*i+1] = cmul(xv[2*i+1], make_float2(kreg[7-i].x, -kreg[7-i].y));
            }
        }
        fft16c_inv(xv);
        #pragma unroll
        for (int r = 0; r < 16; r++) d[pb + r] = xv[r];
    }
    __syncthreads();

    // P2' inv
    {
        float2 xv[32];
        #pragma unroll
        for (int r = 0; r < 32; r++) xv[r] = d[b0 + 17 * r];
        fft32_inv<4, false>(xv, j2);
        #pragma unroll
        for (int r = 0; r < 32; r++) d[b0 + 17 * r] = xv[r];
    }
    __syncthreads();

    // P1' inv: half output, direct global store
    float* o0 = out + ((size_t)(2*p)     * DM + ch) * LSEQ;
    float* o1 = out + ((size_t)(2*p + 1) * DM + ch) * LSEQ;
    {
        float2 xv[32];
        #pragma unroll
        for (int r = 0; r < 32; r++) xv[r] = d[jb + 544 * r];
        fft32_inv<9, true>(xv, tid);
        #pragma unroll
        for (int r = 0; r < 16; r++) {
            const int i = tid + (r << 9);
            o0[i] = xv[r].x;
            o1[i] = xv[r].y;
        }
    }
}

// ---------------- launch ----------------------------------------------------
// Input order (metadata): x, z, t, freq, W1, b1, W2, b2, W3, b3, Wout, deltas, D
extern "C" void kernel_launch(void* const* d_in, const int* in_sizes, int n_in,
                              void* d_out, int out_size) {
    (void)in_sizes; (void)n_in; (void)out_size;
    const float* x      = (const float*)d_in[0];
    const float* z      = (const float*)d_in[1];
    const float* t      = (const float*)d_in[2];
    const float* freq   = (const float*)d_in[3];
    const float* W1     = (const float*)d_in[4];
    const float* b1     = (const float*)d_in[5];
    const float* W2     = (const float*)d_in[6];
    const float* b2     = (const float*)d_in[7];
    const float* W3     = (const float*)d_in[8];
    const float* b3     = (const float*)d_in[9];
    const float* Wout   = (const float*)d_in[10];
    const float* deltas = (const float*)d_in[11];
    const float* Dbias  = (const float*)d_in[12];
    float* out = (float*)d_out;

    cudaFuncSetAttribute(kf_kernel,   cudaFuncAttributeMaxDynamicSharedMemorySize, SMEM_BYTES);
    cudaFuncSetAttribute(conv_kernel, cudaFuncAttributeMaxDynamicSharedMemorySize, SMEM_BYTES);

    mlp_kernel<<<LSEQ / 4, 256>>>(z, freq, W1, b1, W2, b2, W3, b3);
    filt_kernel<<<dim3(LSEQ / 32, DM / 128), 256>>>(Wout, t, deltas);
    kf_kernel<<<DM, NT, SMEM_BYTES>>>(Dbias);
    conv_kernel<<<dim3(2, DM), NT, SMEM_BYTES>>>(x, out);
}

// round 16
// speedup vs baseline: 1.1399x; 1.0284x over previous
#include <cuda_runtime.h>
#include <math.h>

// Problem constants
#define LSEQ 8192
#define NFFT 16384          // 2*LSEQ = 32*32*16
#define DM   768
#define EMB  33
#define FO   64
#define SHIFT_C 0.05f
#define NT   512            // FFT threads per CTA

// Pad 1 float2 per 16: PHYS(i) = i + (i>>4).  (verified conflict-free R5)
#define DPAD 17408
#define SMEM_BYTES (DPAD * (int)sizeof(float2))          // 139264 B

// ---------------- scratch (device globals: no allocations allowed) ----------
__device__ float g_S[LSEQ * FO];                         // post-MLP activations
__device__ float g_k[DM * LSEQ];                         // filter k[d][l]
__device__ __align__(16) float2 g_Kf[(size_t)DM * NFFT]; // (spectrum + D)/N, scrambled,
                                                         // ONLY canonical blocks valid

// cos / (-sin) of 2*pi*k/32 as compile-time constants -> immediate-form FFMA
__device__ static constexpr float CS32[32] = {
    1.0f,                   0.98078528040323044f,  0.92387953251128674f,  0.83146961230254524f,
    0.70710678118654752f,   0.55557023301960222f,  0.38268343236508977f,  0.19509032201612827f,
    0.0f,                  -0.19509032201612827f, -0.38268343236508977f, -0.55557023301960222f,
   -0.70710678118654752f,  -0.83146961230254524f, -0.92387953251128674f, -0.98078528040323044f,
   -1.0f,                  -0.98078528040323044f, -0.92387953251128674f, -0.83146961230254524f,
   -0.70710678118654752f,  -0.55557023301960222f, -0.38268343236508977f, -0.19509032201612827f,
    0.0f,                   0.19509032201612827f,  0.38268343236508977f,  0.55557023301960222f,
    0.70710678118654752f,   0.83146961230254524f,  0.92387953251128674f,  0.98078528040323044f
};
__device__ static constexpr float SN32[32] = {     // = sin(-2*pi*k/32)
    0.0f,                  -0.19509032201612827f, -0.38268343236508977f, -0.55557023301960222f,
   -0.70710678118654752f,  -0.83146961230254524f, -0.92387953251128674f, -0.98078528040323044f,
   -1.0f,                  -0.98078528040323044f, -0.92387953251128674f, -0.83146961230254524f,
   -0.70710678118654752f,  -0.55557023301960222f, -0.38268343236508977f, -0.19509032201612827f,
    0.0f,                   0.19509032201612827f,  0.38268343236508977f,  0.55557023301960222f,
    0.70710678118654752f,   0.83146961230254524f,  0.92387953251128674f,  0.98078528040323044f,
    1.0f,                   0.98078528040323044f,  0.92387953251128674f,  0.83146961230254524f,
    0.70710678118654752f,   0.55557023301960222f,  0.38268343236508977f,  0.19509032201612827f
};

// ---------------- complex helpers ----------------
__device__ __forceinline__ float2 cadd(float2 a, float2 b){ return make_float2(a.x+b.x, a.y+b.y); }
__device__ __forceinline__ float2 csub(float2 a, float2 b){ return make_float2(a.x-b.x, a.y-b.y); }
__device__ __forceinline__ float2 cmul(float2 a, float2 b){
    return make_float2(a.x*b.x - a.y*b.y, a.x*b.y + a.y*b.x);
}
// multiply by compile-time literal (wx, wy): 2 FMUL-imm + 2 FFMA-imm (rt=1)
__device__ __forceinline__ float2 cmuli(float2 a, float wx, float wy) {
    return make_float2(fmaf(a.y, -wy, a.x * wx), fmaf(a.y, wx, a.x * wy));
}
// a * e^{-2*pi*i*k/32}; k folded to constant under #pragma unroll
__device__ __forceinline__ float2 twf(float2 a, int k) {
    k &= 31;
    if (k == 0)  return a;
    if (k == 8)  return make_float2(a.y, -a.x);     // * -i
    if (k == 16) return make_float2(-a.x, -a.y);    // * -1
    if (k == 24) return make_float2(-a.y, a.x);     // * +i
    return cmuli(a, CS32[k], SN32[k]);
}
// a * e^{+2*pi*i*k/32}
__device__ __forceinline__ float2 twb(float2 a, int k) {
    k &= 31;
    if (k == 0)  return a;
    if (k == 8)  return make_float2(-a.y, a.x);     // * +i
    if (k == 16) return make_float2(-a.x, -a.y);    // * -1
    if (k == 24) return make_float2(a.y, -a.x);     // * -i
    return cmuli(a, CS32[k], -SN32[k]);
}

// radix-4 DIF forward core (no twiddle)
__device__ __forceinline__ void bf4f(float2 x0, float2 x1, float2 x2, float2 x3,
                                     float2& a0, float2& a1, float2& a2, float2& a3) {
    float2 t0 = cadd(x0, x2), t1 = csub(x0, x2);
    float2 t2 = cadd(x1, x3), t3 = csub(x1, x3);
    float2 mi = make_float2(t3.y, -t3.x);                // -i * t3
    a0 = cadd(t0, t2);
    a1 = cadd(t1, mi);
    a2 = csub(t0, t2);
    a3 = csub(t1, mi);
}
// radix-4 inverse core (unscaled)
__device__ __forceinline__ void bf4i(float2 x0, float2 x1, float2 x2, float2 x3,
                                     float2& a0, float2& a1, float2& a2, float2& a3) {
    float2 t0 = cadd(x0, x2), t1 = csub(x0, x2);
    float2 t2 = cadd(x1, x3), t3 = csub(x1, x3);
    float2 pi = make_float2(-t3.y, t3.x);                // +i * t3
    a0 = cadd(t0, t2);
    a1 = cadd(t1, pi);
    a2 = csub(t0, t2);
    a3 = csub(t1, pi);
}

// ---------------- register radix-32 (4*4*2 DIF), external span S = 1<<LS ----
// Twiddles: w_m = b^m * e^{-2*pi*i*m*c/32}; b powers hoisted, rotations literal.
// HALF: x[16..31] implicitly zero on entry.
template<int LS, bool HALF>
__device__ __forceinline__ void fft32_fwd(float2* x, int j) {
    const float C = -6.2831853071795864769f / (float)(1 << (LS + 5));
    float sb, cb;
    __sincosf(C * (float)j, &sb, &cb);
    const float2 b  = make_float2(cb, sb);
    const float2 b2 = cmul(b, b);
    const float2 b3 = cmul(b2, b);
    // stage A: span 8
    #pragma unroll
    for (int c = 0; c < 8; c++) {
        float2 w1 = twf(b,  c);
        float2 w2 = twf(b2, 2 * c);
        float2 w3 = twf(b3, 3 * c);
        float2 a0, a1, a2, a3;
        if (HALF) {
            float2 x0 = x[c], x1 = x[c + 8];
            a0 = cadd(x0, x1);
            a1 = make_float2(x0.x + x1.y, x0.y - x1.x);  // x0 - i*x1
            a2 = csub(x0, x1);
            a3 = make_float2(x0.x - x1.y, x0.y + x1.x);  // x0 + i*x1
        } else {
            bf4f(x[c], x[c+8], x[c+16], x[c+24], a0, a1, a2, a3);
        }
        x[c]      = a0;
        x[c + 8]  = cmul(a1, w1);
        x[c + 16] = cmul(a2, w2);
        x[c + 24] = cmul(a3, w3);
    }
    const float2 b4  = cmul(b2, b2);
    const float2 b8  = cmul(b4, b4);
    const float2 b12 = cmul(b8, b4);
    const float2 b16 = cmul(b8, b8);
    // stage B: span 2; twiddles b4^m * e^{-2*pi*i*4*m*c2/32}
    float2 W1[2], W2[2], W3[2];
    W1[0] = b4;  W2[0] = b8;  W3[0] = b12;
    W1[1] = twf(b4, 4);  W2[1] = twf(b8, 8);  W3[1] = twf(b12, 12);
    #pragma unroll
    for (int g = 0; g < 4; g++) {
        #pragma unroll
        for (int c2 = 0; c2 < 2; c2++) {
            const int i = 8 * g + c2;
            float2 a0, a1, a2, a3;
            bf4f(x[i], x[i+2], x[i+4], x[i+6], a0, a1, a2, a3);
            x[i]     = a0;
            x[i + 2] = cmul(a1, W1[c2]);
            x[i + 4] = cmul(a2, W2[c2]);
            x[i + 6] = cmul(a3, W3[c2]);
        }
    }
    // stage C: radix-2, span 1
    #pragma unroll
    for (int m = 0; m < 16; m++) {
        float2 x0 = x[2*m], x1 = x[2*m + 1];
        x[2*m]     = cadd(x0, x1);
        x[2*m + 1] = cmul(csub(x0, x1), b16);
    }
}

// Inverse (unscaled, gain 32).  HALFOUT: only outputs r<16 are produced.
template<int LS, bool HALFOUT>
__device__ __forceinline__ void fft32_inv(float2* x, int j) {
    const float C = -6.2831853071795864769f / (float)(1 << (LS + 5));
    float sb, cb;
    __sincosf(C * (float)j, &sb, &cb);
    const float2 b   = make_float2(cb, -sb);             // conj base
    const float2 b2  = cmul(b, b);
    const float2 b3  = cmul(b2, b);
    const float2 b4  = cmul(b2, b2);
    const float2 b8  = cmul(b4, b4);
    const float2 b12 = cmul(b8, b4);
    const float2 b16 = cmul(b8, b8);
    // stage C'
    #pragma unroll
    for (int m = 0; m < 16; m++) {
        float2 z1 = cmul(x[2*m + 1], b16);
        float2 x0 = x[2*m];
        x[2*m]     = cadd(x0, z1);
        x[2*m + 1] = csub(x0, z1);
    }
    // stage B'
    float2 W1[2], W2[2], W3[2];
    W1[0] = b4;  W2[0] = b8;  W3[0] = b12;
    W1[1] = twb(b4, 4);  W2[1] = twb(b8, 8);  W3[1] = twb(b12, 12);
    #pragma unroll
    for (int g = 0; g < 4; g++) {
        #pragma unroll
        for (int c2 = 0; c2 < 2; c2++) {
            const int i = 8 * g + c2;
            float2 z0 = x[i];
            float2 z1 = cmul(x[i + 2], W1[c2]);
            float2 z2 = cmul(x[i + 4], W2[c2]);
            float2 z3 = cmul(x[i + 6], W3[c2]);
            bf4i(z0, z1, z2, z3, x[i], x[i+2], x[i+4], x[i+6]);
        }
    }
    // stage A'
    #pragma unroll
    for (int c = 0; c < 8; c++) {
        float2 w1 = twb(b,  c);
        float2 w2 = twb(b2, 2 * c);
        float2 w3 = twb(b3, 3 * c);
        float2 z0 = x[c];
        float2 z1 = cmul(x[c + 8],  w1);
        float2 z2 = cmul(x[c + 16], w2);
        float2 z3 = cmul(x[c + 24], w3);
        if (HALFOUT) {
            float2 t0 = cadd(z0, z2), t1 = csub(z0, z2);
            float2 t2 = cadd(z1, z3), t3 = csub(z1, z3);
            float2 pi = make_float2(-t3.y, t3.x);
            x[c]     = cadd(t0, t2);
            x[c + 8] = cadd(t1, pi);
        } else {
            bf4i(z0, z1, z2, z3, x[c], x[c+8], x[c+16], x[c+24]);
        }
    }
}

// ---------------- 16-point cores: ALL twiddles literal ----------------------
__device__ __forceinline__ void fft16c_fwd(float2* x) {
    #pragma unroll
    for (int c = 0; c < 4; c++) {
        float2 a0, a1, a2, a3;
        bf4f(x[c], x[c+4], x[c+8], x[c+12], a0, a1, a2, a3);
        x[c]      = a0;
        x[c + 4]  = twf(a1, 2 * c);
        x[c + 8]  = twf(a2, 4 * c);
        x[c + 12] = twf(a3, 6 * c);
    }
    #pragma unroll
    for (int m = 0; m < 4; m++) {
        float2 a0, a1, a2, a3;
        bf4f(x[4*m], x[4*m+1], x[4*m+2], x[4*m+3], a0, a1, a2, a3);
        x[4*m] = a0; x[4*m+1] = a1; x[4*m+2] = a2; x[4*m+3] = a3;
    }
}
__device__ __forceinline__ void fft16c_inv(float2* x) {
    #pragma unroll
    for (int m = 0; m < 4; m++) {
        float2 a0, a1, a2, a3;
        bf4i(x[4*m], x[4*m+1], x[4*m+2], x[4*m+3], a0, a1, a2, a3);
        x[4*m] = a0; x[4*m+1] = a1; x[4*m+2] = a2; x[4*m+3] = a3;
    }
    #pragma unroll
    for (int c = 0; c < 4; c++) {
        float2 z1 = twb(x[c + 4],  2 * c);
        float2 z2 = twb(x[c + 8],  4 * c);
        float2 z3 = twb(x[c + 12], 6 * c);
        bf4i(x[c], z1, z2, z3, x[c], x[c+4], x[c+8], x[c+12]);
    }
}

// Hermitian partner of a scrambled 16-element block index q (R11-verified):
// (+1)-complement through digit reversal for the 32-groups.
__device__ __forceinline__ int prt32(int m) {
    return (m >= 8) ? (39 - m) : ((m >= 2) ? (9 - m) : 1);
}
__device__ __forceinline__ int partner_block(int q) {
    const int m2 = q & 31, m1 = q >> 5;
    if (m1 >= 1) return (31 - m2) + 32 * prt32(m1);
    if (m2 >= 1) return prt32(m2);
    return 0;
}

// ---------------- filter MLP stages 1-3 (fast-intrinsic sin) -----------------
__global__ void mlp_kernel(const float* __restrict__ z, const float* __restrict__ freq,
                           const float* __restrict__ W1, const float* __restrict__ b1,
                           const float* __restrict__ W2, const float* __restrict__ b2,
                           const float* __restrict__ W3, const float* __restrict__ b3) {
    __shared__ float zs[4][EMB];
    __shared__ float as[4][FO];
    __shared__ float bs[4][FO];
    const int tid = threadIdx.x;
    const int lg  = tid >> 6;
    const int f   = tid & 63;
    const int l   = blockIdx.x * 4 + lg;

    if (f < EMB) zs[lg][f] = z[l * EMB + f];
    __syncthreads();

    const float fr = freq[f];

    float acc = b1[f];
    #pragma unroll
    for (int e = 0; e < EMB; e++) acc += zs[lg][e] * W1[e * FO + f];
    as[lg][f] = __sinf(fr * acc);
    __syncthreads();

    acc = b2[f];
    #pragma unroll
    for (int e = 0; e < FO; e++) acc += as[lg][e] * W2[e * FO + f];
    bs[lg][f] = __sinf(fr * acc);
    __syncthreads();

    acc = b3[f];
    #pragma unroll
    for (int e = 0; e < FO; e++) acc += bs[lg][e] * W3[e * FO + f];
    g_S[l * FO + f] = __sinf(fr * acc);
}

// ---------------- output projection + exponential modulation ----------------
__global__ void filt_kernel(const float* __restrict__ Wout, const float* __restrict__ t,
                            const float* __restrict__ deltas) {
    __shared__ float Ss[32][FO];
    __shared__ float Ws[FO][128];
    const int tid = threadIdx.x;
    const int l0  = blockIdx.x * 32;
    const int d0  = blockIdx.y * 128;

    for (int i = tid; i < 32 * FO; i += 256)
        Ss[i >> 6][i & 63] = g_S[(l0 + (i >> 6)) * FO + (i & 63)];
    for (int i = tid; i < FO * 128; i += 256)
        Ws[i >> 7][i & 127] = Wout[(i >> 7) * DM + d0 + (i & 127)];
    __syncthreads();

    const int dl  = tid & 127;
    const int lgp = tid >> 7;
    float acc[16];
    #pragma unroll
    for (int i = 0; i < 16; i++) acc[i] = 0.0f;
    #pragma unroll
    for (int f = 0; f < FO; f++) {
        const float w = Ws[f][dl];
        #pragma unroll
        for (int i = 0; i < 16; i++) acc[i] += Ss[lgp * 16 + i][f] * w;
    }
    const int d = d0 + dl;
    const float ad = fabsf(deltas[d]);
    const int lbase = l0 + lgp * 16;
    float e = __expf(-t[lbase] * ad);
    const float rr = __expf(-ad * (1.0f / 8191.0f));
    float* kout = g_k + (size_t)d * LSEQ + lbase;
    #pragma unroll
    for (int i = 0; i < 16; i++) {
        kout[i] = acc[i] * (e + SHIFT_C);
        e *= rr;
    }
}

// ---------------- kernel spectra: 2 channels per FFT, canonical-only out ----
// Pack z = k_{2cp} + i*k_{2cp+1}.  After P1/P2 the smem holds pre-fwd16 blocks.
// Canonical threads fwd16 BOTH their block q and partner qb in registers (no
// store-back pass), Hermitian-split, bake (+D)/N, write canonical blocks only.
__global__ void __launch_bounds__(NT, 1)
kf_kernel(const float* __restrict__ Dbias) {
    extern __shared__ float2 d[];
    const int tid = threadIdx.x;
    const int cp  = blockIdx.x;                          // channel pair
    const int chA = 2 * cp, chB = 2 * cp + 1;

    const float* krowA = g_k + (size_t)chA * LSEQ;
    const float* krowB = g_k + (size_t)chB * LSEQ;
    const int jb = tid + (tid >> 4);                     // PHYS(tid)

    // P1: radix-32, S=512; pack kA + i*kB; top half zero
    {
        float2 xv[32];
        #pragma unroll
        for (int r = 0; r < 16; r++) {
            const int i = tid + (r << 9);
            xv[r] = make_float2(krowA[i], krowB[i]);
        }
        fft32_fwd<9, true>(xv, tid);
        #pragma unroll
        for (int r = 0; r < 32; r++) d[jb + 544 * r] = xv[r];
    }
    __syncthreads();

    const int j2 = tid & 15;
    const int b0 = (tid >> 4) * 544 + j2;

    // P2: radix-32, S=16
    {
        float2 xv[32];
        #pragma unroll
        for (int r = 0; r < 32; r++) xv[r] = d[b0 + 17 * r];
        fft32_fwd<4, false>(xv, j2);
        #pragma unroll
        for (int r = 0; r < 32; r++) d[b0 + 17 * r] = xv[r];
    }
    __syncthreads();

    // P3': canonical blocks: fwd16 of q AND qb in registers, split, write.
    const float sc = 1.0f / (float)NFFT;
    const float DA = Dbias[chA], DB = Dbias[chB];
    float2* outA = g_Kf + (size_t)chA * NFFT;
    float2* outB = g_Kf + (size_t)chB * NFFT;
    #pragma unroll
    for (int k = 0; k < 2; k++) {
        const int q  = tid + k * NT;
        const int qb = partner_block(q);
        if (q > qb) continue;                            // non-canonical: skip
        float2 za[16], zb[16];
        {
            const int pb = 17 * q;
            #pragma unroll
            for (int r = 0; r < 16; r++) za[r] = d[pb + r];
            fft16c_fwd(za);
        }
        {
            const int pbb = 17 * qb;
            #pragma unroll
            for (int r = 0; r < 16; r++) zb[r] = d[pbb + r];
            fft16c_fwd(zb);
        }
        float4* oA = reinterpret_cast<float4*>(outA + 16 * q);
        float4* oB = reinterpret_cast<float4*>(outB + 16 * q);
        if (q == 0) {
            // special in-block map: m3b = 0 | 19-m3 (m3>=4) | 4-m3 (1<=m3<=3)
            #pragma unroll
            for (int i = 0; i < 8; i++) {
                float kax[2], kay[2], kbx[2], kby[2];
                #pragma unroll
                for (int h = 0; h < 2; h++) {
                    const int m3  = 2 * i + h;
                    const int m3b = (m3 == 0) ? 0 : ((m3 >= 4) ? (19 - m3) : (4 - m3));
                    const float a = za[m3].x, bb = za[m3].y;
                    const float c = zb[m3b].x, dd = zb[m3b].y;
                    kax[h] = 0.5f * (a + c);   kay[h] = 0.5f * (bb - dd);
                    kbx[h] = 0.5f * (bb + dd); kby[h] = 0.5f * (c - a);
                }
                oA[i] = make_float4((kax[0] + DA) * sc, kay[0] * sc,
                                    (kax[1] + DA) * sc, kay[1] * sc);
                oB[i] = make_float4((kbx[0] + DB) * sc, kby[0] * sc,
                                    (kbx[1] + DB) * sc, kby[1] * sc);
            }
        } else {
            // standard in-block reversal: m3b = 15 - m3
            #pragma unroll
            for (int i = 0; i < 8; i++) {
                float kax[2], kay[2], kbx[2], kby[2];
                #pragma unroll
                for (int h = 0; h < 2; h++) {
                    const int m3  = 2 * i + h;
                    const int m3b = 15 - m3;
                    const float a = za[m3].x, bb = za[m3].y;
                    const float c = zb[m3b].x, dd = zb[m3b].y;
                    kax[h] = 0.5f * (a + c);   kay[h] = 0.5f * (bb - dd);
                    kbx[h] = 0.5f * (bb + dd); kby[h] = 0.5f * (c - a);
                }
                oA[i] = make_float4((kax[0] + DA) * sc, kay[0] * sc,
                                    (kax[1] + DA) * sc, kay[1] * sc);
                oB[i] = make_float4((kbx[0] + DB) * sc, kby[0] * sc,
                                    (kbx[1] + DB) * sc, kby[1] * sc);
            }
        }
    }
}

// ---------------- conv ------------------------------------------------------
// grid = dim3(2, DM): twin CTAs per channel adjacent -> Kf L2 sharing.
// Kf holds only canonical blocks; non-canonical threads reconstruct via
// reversed-conjugate of the partner block (static pattern).
__global__ void __launch_bounds__(NT, 1)
conv_kernel(const float* __restrict__ x, float* __restrict__ out) {
    extern __shared__ float2 d[];
    const int tid = threadIdx.x;
    const int ch  = blockIdx.y;
    const int p   = blockIdx.x;                          // batch pair

    const float* u0 = x + ((size_t)(2*p)     * DM + ch) * LSEQ;
    const float* u1 = x + ((size_t)(2*p + 1) * DM + ch) * LSEQ;
    const float2* kf = g_Kf + (size_t)ch * NFFT;

    // prefetch effective (canonical) Kf lines into L2
    {
        const int qe0 = min(tid, partner_block(tid));
        const int qe1 = min(tid + NT, partner_block(tid + NT));
        asm volatile("prefetch.global.L2 [%0];" :: "l"(kf + 16 * qe0));
        asm volatile("prefetch.global.L2 [%0];" :: "l"(kf + 16 * qe1));
    }

    const int jb = tid + (tid >> 4);

    // P1 fwd: radix-32, S=512; pack u0 + i*u1; top half zero
    {
        float2 xv[32];
        #pragma unroll
        for (int r = 0; r < 16; r++) {
            const int i = tid + (r << 9);
            xv[r] = make_float2(u0[i], u1[i]);
        }
        fft32_fwd<9, true>(xv, tid);
        #pragma unroll
        for (int r = 0; r < 32; r++) d[jb + 544 * r] = xv[r];
    }
    __syncthreads();

    const int j2 = tid & 15;
    const int b0 = (tid >> 4) * 544 + j2;

    // P2 fwd: radix-32, S=16
    {
        float2 xv[32];
        #pragma unroll
        for (int r = 0; r < 32; r++) xv[r] = d[b0 + 17 * r];
        fft32_fwd<4, false>(xv, j2);
        #pragma unroll
        for (int r = 0; r < 32; r++) d[b0 + 17 * r] = xv[r];
    }
    __syncthreads();

    // P3: const-twiddle fwd16 -> * Kf (Hermitian-half) -> const-twiddle inv16
    #pragma unroll
    for (int k = 0; k < 2; k++) {
        const int q  = tid + k * NT;
        const int pb = 17 * q;
        const int qb = partner_block(q);
        const bool canon = (q <= qb);
        const int qe = canon ? q : qb;
        float4 kreg[8];
        const float4* kf4 = reinterpret_cast<const float4*>(kf + 16 * qe);
        #pragma unroll
        for (int i = 0; i < 8; i++) kreg[i] = kf4[i];    // prefetch over fwd16
        float2 xv[16];
        #pragma unroll
        for (int r = 0; r < 16; r++) xv[r] = d[pb + r];
        fft16c_fwd(xv);
        if (canon) {
            #pragma unroll
            for (int i = 0; i < 8; i++) {
                xv[2*i]   = cmul(xv[2*i],   make_float2(kreg[i].x, kreg[i].y));
                xv[2*i+1] = cmul(xv[2*i+1], make_float2(kreg[i].z, kreg[i].w));
            }
        } else {
            // needed[m3] = conj(stored[15 - m3]):
            //   m3=2i   -> conj(kreg[7-i].zw)
            //   m3=2i+1 -> conj(kreg[7-i].xy)
            #pragma unroll
            for (int i = 0; i < 8; i++) {
                xv[2*i]   = cmul(xv[2*i],   make_float2(kreg[7-i].z, -kreg[7-i].w));
                xv[2*i+1] = cmul(xv[2*i+1], make_float2(kreg[7-i].x, -kreg[7-i].y));
            }
        }
        fft16c_inv(xv);
        #pragma unroll
        for (int r = 0; r < 16; r++) d[pb + r] = xv[r];
    }
    __syncthreads();

    // P2' inv
    {
        float2 xv[32];
        #pragma unroll
        for (int r = 0; r < 32; r++) xv[r] = d[b0 + 17 * r];
        fft32_inv<4, false>(xv, j2);
        #pragma unroll
        for (int r = 0; r < 32; r++) d[b0 + 17 * r] = xv[r];
    }
    __syncthreads();

    // P1' inv: half output, direct global store
    float* o0 = out + ((size_t)(2*p)     * DM + ch) * LSEQ;
    float* o1 = out + ((size_t)(2*p + 1) * DM + ch) * LSEQ;
    {
        float2 xv[32];
        #pragma unroll
        for (int r = 0; r < 32; r++) xv[r] = d[jb + 544 * r];
        fft32_inv<9, true>(xv, tid);
        #pragma unroll
        for (int r = 0; r < 16; r++) {
            const int i = tid + (r << 9);
            o0[i] = xv[r].x;
            o1[i] = xv[r].y;
        }
    }
}

// ---------------- launch ----------------------------------------------------
// Input order (metadata): x, z, t, freq, W1, b1, W2, b2, W3, b3, Wout, deltas, D
extern "C" void kernel_launch(void* const* d_in, const int* in_sizes, int n_in,
                              void* d_out, int out_size) {
    (void)in_sizes; (void)n_in; (void)out_size;
    const float* x      = (const float*)d_in[0];
    const float* z      = (const float*)d_in[1];
    const float* t      = (const float*)d_in[2];
    const float* freq   = (const float*)d_in[3];
    const float* W1     = (const float*)d_in[4];
    const float* b1     = (const float*)d_in[5];
    const float* W2     = (const float*)d_in[6];
    const float* b2     = (const float*)d_in[7];
    const float* W3     = (const float*)d_in[8];
    const float* b3     = (const float*)d_in[9];
    const float* Wout   = (const float*)d_in[10];
    const float* deltas = (const float*)d_in[11];
    const float* Dbias  = (const float*)d_in[12];
    float* out = (float*)d_out;

    cudaFuncSetAttribute(kf_kernel,   cudaFuncAttributeMaxDynamicSharedMemorySize, SMEM_BYTES);
    cudaFuncSetAttribute(conv_kernel, cudaFuncAttributeMaxDynamicSharedMemorySize, SMEM_BYTES);

    mlp_kernel<<<LSEQ / 4, 256>>>(z, freq, W1, b1, W2, b2, W3, b3);
    filt_kernel<<<dim3(LSEQ / 32, DM / 128), 256>>>(Wout, t, deltas);
    kf_kernel<<<DM / 2, NT, SMEM_BYTES>>>(Dbias);
    conv_kernel<<<dim3(2, DM), NT, SMEM_BYTES>>>(x, out);
}

// round 17
// speedup vs baseline: 1.1897x; 1.0437x over previous
#include <cuda_runtime.h>
#include <math.h>

// Problem constants
#define LSEQ 8192
#define NFFT 16384          // 2*LSEQ = 32*32*16
#define DM   768
#define EMB  33
#define FO   64
#define SHIFT_C 0.05f
#define NT   512            // FFT threads per CTA

// Pad 1 float2 per 16: PHYS(i) = i + (i>>4).  (verified conflict-free R5)
#define DPAD 17408
#define SMEM_BYTES (DPAD * (int)sizeof(float2))          // 139264 B

// ---------------- scratch (device globals: no allocations allowed) ----------
__device__ float g_S[LSEQ * FO];                         // post-MLP activations
__device__ float g_k[DM * LSEQ];                         // filter k[d][l]
__device__ __align__(16) float2 g_Kf[(size_t)DM * NFFT]; // (spectrum + D)/N, scrambled,
                                                         // ONLY canonical blocks valid

// cos / (-sin) of 2*pi*k/32 as compile-time constants -> immediate-form FFMA
__device__ static constexpr float CS32[32] = {
    1.0f,                   0.98078528040323044f,  0.92387953251128674f,  0.83146961230254524f,
    0.70710678118654752f,   0.55557023301960222f,  0.38268343236508977f,  0.19509032201612827f,
    0.0f,                  -0.19509032201612827f, -0.38268343236508977f, -0.55557023301960222f,
   -0.70710678118654752f,  -0.83146961230254524f, -0.92387953251128674f, -0.98078528040323044f,
   -1.0f,                  -0.98078528040323044f, -0.92387953251128674f, -0.83146961230254524f,
   -0.70710678118654752f,  -0.55557023301960222f, -0.38268343236508977f, -0.19509032201612827f,
    0.0f,                   0.19509032201612827f,  0.38268343236508977f,  0.55557023301960222f,
    0.70710678118654752f,   0.83146961230254524f,  0.92387953251128674f,  0.98078528040323044f
};
__device__ static constexpr float SN32[32] = {     // = sin(-2*pi*k/32)
    0.0f,                  -0.19509032201612827f, -0.38268343236508977f, -0.55557023301960222f,
   -0.70710678118654752f,  -0.83146961230254524f, -0.92387953251128674f, -0.98078528040323044f,
   -1.0f,                  -0.98078528040323044f, -0.92387953251128674f, -0.83146961230254524f,
   -0.70710678118654752f,  -0.55557023301960222f, -0.38268343236508977f, -0.19509032201612827f,
    0.0f,                   0.19509032201612827f,  0.38268343236508977f,  0.55557023301960222f,
    0.70710678118654752f,   0.83146961230254524f,  0.92387953251128674f,  0.98078528040323044f,
    1.0f,                   0.98078528040323044f,  0.92387953251128674f,  0.83146961230254524f,
    0.70710678118654752f,   0.55557023301960222f,  0.38268343236508977f,  0.19509032201612827f
};

// ---------------- complex helpers ----------------
__device__ __forceinline__ float2 cadd(float2 a, float2 b){ return make_float2(a.x+b.x, a.y+b.y); }
__device__ __forceinline__ float2 csub(float2 a, float2 b){ return make_float2(a.x-b.x, a.y-b.y); }
__device__ __forceinline__ float2 cmul(float2 a, float2 b){
    return make_float2(a.x*b.x - a.y*b.y, a.x*b.y + a.y*b.x);
}
// multiply by compile-time literal (wx, wy): 2 FMUL-imm + 2 FFMA-imm (rt=1)
__device__ __forceinline__ float2 cmuli(float2 a, float wx, float wy) {
    return make_float2(fmaf(a.y, -wy, a.x * wx), fmaf(a.y, wx, a.x * wy));
}
// a * e^{-2*pi*i*k/32}; k folded to constant under #pragma unroll
__device__ __forceinline__ float2 twf(float2 a, int k) {
    k &= 31;
    if (k == 0)  return a;
    if (k == 8)  return make_float2(a.y, -a.x);     // * -i
    if (k == 16) return make_float2(-a.x, -a.y);    // * -1
    if (k == 24) return make_float2(-a.y, a.x);     // * +i
    return cmuli(a, CS32[k], SN32[k]);
}
// a * e^{+2*pi*i*k/32}
__device__ __forceinline__ float2 twb(float2 a, int k) {
    k &= 31;
    if (k == 0)  return a;
    if (k == 8)  return make_float2(-a.y, a.x);     // * +i
    if (k == 16) return make_float2(-a.x, -a.y);    // * -1
    if (k == 24) return make_float2(a.y, -a.x);     // * -i
    return cmuli(a, CS32[k], -SN32[k]);
}

// radix-4 DIF forward core (no twiddle)
__device__ __forceinline__ void bf4f(float2 x0, float2 x1, float2 x2, float2 x3,
                                     float2& a0, float2& a1, float2& a2, float2& a3) {
    float2 t0 = cadd(x0, x2), t1 = csub(x0, x2);
    float2 t2 = cadd(x1, x3), t3 = csub(x1, x3);
    float2 mi = make_float2(t3.y, -t3.x);                // -i * t3
    a0 = cadd(t0, t2);
    a1 = cadd(t1, mi);
    a2 = csub(t0, t2);
    a3 = csub(t1, mi);
}
// radix-4 inverse core (unscaled)
__device__ __forceinline__ void bf4i(float2 x0, float2 x1, float2 x2, float2 x3,
                                     float2& a0, float2& a1, float2& a2, float2& a3) {
    float2 t0 = cadd(x0, x2), t1 = csub(x0, x2);
    float2 t2 = cadd(x1, x3), t3 = csub(x1, x3);
    float2 pi = make_float2(-t3.y, t3.x);                // +i * t3
    a0 = cadd(t0, t2);
    a1 = cadd(t1, pi);
    a2 = csub(t0, t2);
    a3 = csub(t1, pi);
}

// ---------------- register radix-32 (4*4*2 DIF), external span S = 1<<LS ----
// Twiddles: w_m = b^m * e^{-2*pi*i*m*c/32}; b powers hoisted, rotations literal.
// HALF: x[16..31] implicitly zero on entry.
template<int LS, bool HALF>
__device__ __forceinline__ void fft32_fwd(float2* x, int j) {
    const float C = -6.2831853071795864769f / (float)(1 << (LS + 5));
    float sb, cb;
    __sincosf(C * (float)j, &sb, &cb);
    const float2 b  = make_float2(cb, sb);
    const float2 b2 = cmul(b, b);
    const float2 b3 = cmul(b2, b);
    // stage A: span 8
    #pragma unroll
    for (int c = 0; c < 8; c++) {
        float2 w1 = twf(b,  c);
        float2 w2 = twf(b2, 2 * c);
        float2 w3 = twf(b3, 3 * c);
        float2 a0, a1, a2, a3;
        if (HALF) {
            float2 x0 = x[c], x1 = x[c + 8];
            a0 = cadd(x0, x1);
            a1 = make_float2(x0.x + x1.y, x0.y - x1.x);  // x0 - i*x1
            a2 = csub(x0, x1);
            a3 = make_float2(x0.x - x1.y, x0.y + x1.x);  // x0 + i*x1
        } else {
            bf4f(x[c], x[c+8], x[c+16], x[c+24], a0, a1, a2, a3);
        }
        x[c]      = a0;
        x[c + 8]  = cmul(a1, w1);
        x[c + 16] = cmul(a2, w2);
        x[c + 24] = cmul(a3, w3);
    }
    const float2 b4  = cmul(b2, b2);
    const float2 b8  = cmul(b4, b4);
    const float2 b12 = cmul(b8, b4);
    const float2 b16 = cmul(b8, b8);
    // stage B: span 2; twiddles b4^m * e^{-2*pi*i*4*m*c2/32}
    float2 W1[2], W2[2], W3[2];
    W1[0] = b4;  W2[0] = b8;  W3[0] = b12;
    W1[1] = twf(b4, 4);  W2[1] = twf(b8, 8);  W3[1] = twf(b12, 12);
    #pragma unroll
    for (int g = 0; g < 4; g++) {
        #pragma unroll
        for (int c2 = 0; c2 < 2; c2++) {
            const int i = 8 * g + c2;
            float2 a0, a1, a2, a3;
            bf4f(x[i], x[i+2], x[i+4], x[i+6], a0, a1, a2, a3);
            x[i]     = a0;
            x[i + 2] = cmul(a1, W1[c2]);
            x[i + 4] = cmul(a2, W2[c2]);
            x[i + 6] = cmul(a3, W3[c2]);
        }
    }
    // stage C: radix-2, span 1
    #pragma unroll
    for (int m = 0; m < 16; m++) {
        float2 x0 = x[2*m], x1 = x[2*m + 1];
        x[2*m]     = cadd(x0, x1);
        x[2*m + 1] = cmul(csub(x0, x1), b16);
    }
}

// Inverse (unscaled, gain 32).  HALFOUT: only outputs r<16 are produced.
template<int LS, bool HALFOUT>
__device__ __forceinline__ void fft32_inv(float2* x, int j) {
    const float C = -6.2831853071795864769f / (float)(1 << (LS + 5));
    float sb, cb;
    __sincosf(C * (float)j, &sb, &cb);
    const float2 b   = make_float2(cb, -sb);             // conj base
    const float2 b2  = cmul(b, b);
    const float2 b3  = cmul(b2, b);
    const float2 b4  = cmul(b2, b2);
    const float2 b8  = cmul(b4, b4);
    const float2 b12 = cmul(b8, b4);
    const float2 b16 = cmul(b8, b8);
    // stage C'
    #pragma unroll
    for (int m = 0; m < 16; m++) {
        float2 z1 = cmul(x[2*m + 1], b16);
        float2 x0 = x[2*m];
        x[2*m]     = cadd(x0, z1);
        x[2*m + 1] = csub(x0, z1);
    }
    // stage B'
    float2 W1[2], W2[2], W3[2];
    W1[0] = b4;  W2[0] = b8;  W3[0] = b12;
    W1[1] = twb(b4, 4);  W2[1] = twb(b8, 8);  W3[1] = twb(b12, 12);
    #pragma unroll
    for (int g = 0; g < 4; g++) {
        #pragma unroll
        for (int c2 = 0; c2 < 2; c2++) {
            const int i = 8 * g + c2;
            float2 z0 = x[i];
            float2 z1 = cmul(x[i + 2], W1[c2]);
            float2 z2 = cmul(x[i + 4], W2[c2]);
            float2 z3 = cmul(x[i + 6], W3[c2]);
            bf4i(z0, z1, z2, z3, x[i], x[i+2], x[i+4], x[i+6]);
        }
    }
    // stage A'
    #pragma unroll
    for (int c = 0; c < 8; c++) {
        float2 w1 = twb(b,  c);
        float2 w2 = twb(b2, 2 * c);
        float2 w3 = twb(b3, 3 * c);
        float2 z0 = x[c];
        float2 z1 = cmul(x[c + 8],  w1);
        float2 z2 = cmul(x[c + 16], w2);
        float2 z3 = cmul(x[c + 24], w3);
        if (HALFOUT) {
            float2 t0 = cadd(z0, z2), t1 = csub(z0, z2);
            float2 t2 = cadd(z1, z3), t3 = csub(z1, z3);
            float2 pi = make_float2(-t3.y, t3.x);
            x[c]     = cadd(t0, t2);
            x[c + 8] = cadd(t1, pi);
        } else {
            bf4i(z0, z1, z2, z3, x[c], x[c+8], x[c+16], x[c+24]);
        }
    }
}

// ---------------- 16-point cores: ALL twiddles literal ----------------------
__device__ __forceinline__ void fft16c_fwd(float2* x) {
    #pragma unroll
    for (int c = 0; c < 4; c++) {
        float2 a0, a1, a2, a3;
        bf4f(x[c], x[c+4], x[c+8], x[c+12], a0, a1, a2, a3);
        x[c]      = a0;
        x[c + 4]  = twf(a1, 2 * c);
        x[c + 8]  = twf(a2, 4 * c);
        x[c + 12] = twf(a3, 6 * c);
    }
    #pragma unroll
    for (int m = 0; m < 4; m++) {
        float2 a0, a1, a2, a3;
        bf4f(x[4*m], x[4*m+1], x[4*m+2], x[4*m+3], a0, a1, a2, a3);
        x[4*m] = a0; x[4*m+1] = a1; x[4*m+2] = a2; x[4*m+3] = a3;
    }
}
__device__ __forceinline__ void fft16c_inv(float2* x) {
    #pragma unroll
    for (int m = 0; m < 4; m++) {
        float2 a0, a1, a2, a3;
        bf4i(x[4*m], x[4*m+1], x[4*m+2], x[4*m+3], a0, a1, a2, a3);
        x[4*m] = a0; x[4*m+1] = a1; x[4*m+2] = a2; x[4*m+3] = a3;
    }
    #pragma unroll
    for (int c = 0; c < 4; c++) {
        float2 z1 = twb(x[c + 4],  2 * c);
        float2 z2 = twb(x[c + 8],  4 * c);
        float2 z3 = twb(x[c + 12], 6 * c);
        bf4i(x[c], z1, z2, z3, x[c], x[c+4], x[c+8], x[c+12]);
    }
}

// Hermitian partner of a scrambled 16-element block index q (R11-verified):
// (+1)-complement through digit reversal for the 32-groups.
__device__ __forceinline__ int prt32(int m) {
    return (m >= 8) ? (39 - m) : ((m >= 2) ? (9 - m) : 1);
}
__device__ __forceinline__ int partner_block(int q) {
    const int m2 = q & 31, m1 = q >> 5;
    if (m1 >= 1) return (31 - m2) + 32 * prt32(m1);
    if (m2 >= 1) return prt32(m2);
    return 0;
}

// ---------------- filter MLP stages 1-3 (fast-intrinsic sin) -----------------
__global__ void mlp_kernel(const float* __restrict__ z, const float* __restrict__ freq,
                           const float* __restrict__ W1, const float* __restrict__ b1,
                           const float* __restrict__ W2, const float* __restrict__ b2,
                           const float* __restrict__ W3, const float* __restrict__ b3) {
    __shared__ float zs[4][EMB];
    __shared__ float as[4][FO];
    __shared__ float bs[4][FO];
    const int tid = threadIdx.x;
    const int lg  = tid >> 6;
    const int f   = tid & 63;
    const int l   = blockIdx.x * 4 + lg;

    if (f < EMB) zs[lg][f] = z[l * EMB + f];
    __syncthreads();

    const float fr = freq[f];

    float acc = b1[f];
    #pragma unroll
    for (int e = 0; e < EMB; e++) acc += zs[lg][e] * W1[e * FO + f];
    as[lg][f] = __sinf(fr * acc);
    __syncthreads();

    acc = b2[f];
    #pragma unroll
    for (int e = 0; e < FO; e++) acc += as[lg][e] * W2[e * FO + f];
    bs[lg][f] = __sinf(fr * acc);
    __syncthreads();

    acc = b3[f];
    #pragma unroll
    for (int e = 0; e < FO; e++) acc += bs[lg][e] * W3[e * FO + f];
    g_S[l * FO + f] = __sinf(fr * acc);
}

// ---------------- output projection + exponential modulation ----------------
// GEMM restructured LDS-lean: f processed in groups of 4; Ws scalars hoisted,
// Ss rows read as LDS.128 (256B-aligned rows, broadcast within lgp half).
// 320 LDS vs 1024 FMA per thread (was 1088:1024).
__global__ void filt_kernel(const float* __restrict__ Wout, const float* __restrict__ t,
                            const float* __restrict__ deltas) {
    __shared__ __align__(16) float Ss[32][FO];
    __shared__ float Ws[FO][128];
    const int tid = threadIdx.x;
    const int l0  = blockIdx.x * 32;
    const int d0  = blockIdx.y * 128;

    // vectorized Ss load: 32*64 floats = 512 float4 (g_S rows contiguous)
    {
        const float4* src = reinterpret_cast<const float4*>(g_S + (size_t)l0 * FO);
        float4* dst = reinterpret_cast<float4*>(&Ss[0][0]);
        for (int i = tid; i < 32 * FO / 4; i += 256) dst[i] = src[i];
    }
    for (int i = tid; i < FO * 128; i += 256)
        Ws[i >> 7][i & 127] = Wout[(i >> 7) * DM + d0 + (i & 127)];
    __syncthreads();

    const int dl  = tid & 127;
    const int lgp = tid >> 7;
    float acc[16];
    #pragma unroll
    for (int i = 0; i < 16; i++) acc[i] = 0.0f;
    #pragma unroll
    for (int fb = 0; fb < 16; fb++) {
        const float w0 = Ws[4*fb + 0][dl];
        const float w1 = Ws[4*fb + 1][dl];
        const float w2 = Ws[4*fb + 2][dl];
        const float w3 = Ws[4*fb + 3][dl];
        #pragma unroll
        for (int i = 0; i < 16; i++) {
            const float4 s = *reinterpret_cast<const float4*>(&Ss[lgp * 16 + i][4 * fb]);
            acc[i] = fmaf(s.x, w0, fmaf(s.y, w1, fmaf(s.z, w2, fmaf(s.w, w3, acc[i]))));
        }
    }
    const int d = d0 + dl;
    const float ad = fabsf(deltas[d]);
    const int lbase = l0 + lgp * 16;
    float e = __expf(-t[lbase] * ad);
    const float rr = __expf(-ad * (1.0f / 8191.0f));
    float* kout = g_k + (size_t)d * LSEQ + lbase;
    #pragma unroll
    for (int i = 0; i < 16; i++) {
        kout[i] = acc[i] * (e + SHIFT_C);
        e *= rr;
    }
}

// ---------------- kernel spectra: 2 channels per FFT, canonical-only out ----
__global__ void __launch_bounds__(NT, 1)
kf_kernel(const float* __restrict__ Dbias) {
    extern __shared__ float2 d[];
    const int tid = threadIdx.x;
    const int cp  = blockIdx.x;                          // channel pair
    const int chA = 2 * cp, chB = 2 * cp + 1;

    const float* krowA = g_k + (size_t)chA * LSEQ;
    const float* krowB = g_k + (size_t)chB * LSEQ;
    const int jb = tid + (tid >> 4);                     // PHYS(tid)

    // P1: radix-32, S=512; pack kA + i*kB; top half zero
    {
        float2 xv[32];
        #pragma unroll
        for (int r = 0; r < 16; r++) {
            const int i = tid + (r << 9);
            xv[r] = make_float2(krowA[i], krowB[i]);
        }
        fft32_fwd<9, true>(xv, tid);
        #pragma unroll
        for (int r = 0; r < 32; r++) d[jb + 544 * r] = xv[r];
    }
    __syncthreads();

    const int j2 = tid & 15;
    const int b0 = (tid >> 4) * 544 + j2;

    // P2: radix-32, S=16
    {
        float2 xv[32];
        #pragma unroll
        for (int r = 0; r < 32; r++) xv[r] = d[b0 + 17 * r];
        fft32_fwd<4, false>(xv, j2);
        #pragma unroll
        for (int r = 0; r < 32; r++) d[b0 + 17 * r] = xv[r];
    }
    __syncthreads();

    // P3': canonical blocks: fwd16 of q AND qb in registers, split, write.
    const float sc = 1.0f / (float)NFFT;
    const float DA = Dbias[chA], DB = Dbias[chB];
    float2* outA = g_Kf + (size_t)chA * NFFT;
    float2* outB = g_Kf + (size_t)chB * NFFT;
    #pragma unroll
    for (int k = 0; k < 2; k++) {
        const int q  = tid + k * NT;
        const int qb = partner_block(q);
        if (q > qb) continue;                            // non-canonical: skip
        float2 za[16], zb[16];
        {
            const int pb = 17 * q;
            #pragma unroll
            for (int r = 0; r < 16; r++) za[r] = d[pb + r];
            fft16c_fwd(za);
        }
        {
            const int pbb = 17 * qb;
            #pragma unroll
            for (int r = 0; r < 16; r++) zb[r] = d[pbb + r];
            fft16c_fwd(zb);
        }
        float4* oA = reinterpret_cast<float4*>(outA + 16 * q);
        float4* oB = reinterpret_cast<float4*>(outB + 16 * q);
        if (q == 0) {
            // special in-block map: m3b = 0 | 19-m3 (m3>=4) | 4-m3 (1<=m3<=3)
            #pragma unroll
            for (int i = 0; i < 8; i++) {
                float kax[2], kay[2], kbx[2], kby[2];
                #pragma unroll
                for (int h = 0; h < 2; h++) {
                    const int m3  = 2 * i + h;
                    const int m3b = (m3 == 0) ? 0 : ((m3 >= 4) ? (19 - m3) : (4 - m3));
                    const float a = za[m3].x, bb = za[m3].y;
                    const float c = zb[m3b].x, dd = zb[m3b].y;
                    kax[h] = 0.5f * (a + c);   kay[h] = 0.5f * (bb - dd);
                    kbx[h] = 0.5f * (bb + dd); kby[h] = 0.5f * (c - a);
                }
                oA[i] = make_float4((kax[0] + DA) * sc, kay[0] * sc,
                                    (kax[1] + DA) * sc, kay[1] * sc);
                oB[i] = make_float4((kbx[0] + DB) * sc, kby[0] * sc,
                                    (kbx[1] + DB) * sc, kby[1] * sc);
            }
        } else {
            // standard in-block reversal: m3b = 15 - m3
            #pragma unroll
            for (int i = 0; i < 8; i++) {
                float kax[2], kay[2], kbx[2], kby[2];
                #pragma unroll
                for (int h = 0; h < 2; h++) {
                    const int m3  = 2 * i + h;
                    const int m3b = 15 - m3;
                    const float a = za[m3].x, bb = za[m3].y;
                    const float c = zb[m3b].x, dd = zb[m3b].y;
                    kax[h] = 0.5f * (a + c);   kay[h] = 0.5f * (bb - dd);
                    kbx[h] = 0.5f * (bb + dd); kby[h] = 0.5f * (c - a);
                }
                oA[i] = make_float4((kax[0] + DA) * sc, kay[0] * sc,
                                    (kax[1] + DA) * sc, kay[1] * sc);
                oB[i] = make_float4((kbx[0] + DB) * sc, kby[0] * sc,
                                    (kbx[1] + DB) * sc, kby[1] * sc);
            }
        }
    }
}

// ---------------- conv ------------------------------------------------------
// grid = dim3(2, DM): twin CTAs per channel adjacent -> Kf L2 sharing.
// Kf holds only canonical blocks; non-canonical threads reconstruct via
// reversed-conjugate of the partner block (static pattern).
__global__ void __launch_bounds__(NT, 1)
conv_kernel(const float* __restrict__ x, float* __restrict__ out) {
    extern __shared__ float2 d[];
    const int tid = threadIdx.x;
    const int ch  = blockIdx.y;
    const int p   = blockIdx.x;                          // batch pair

    const float* u0 = x + ((size_t)(2*p)     * DM + ch) * LSEQ;
    const float* u1 = x + ((size_t)(2*p + 1) * DM + ch) * LSEQ;
    const float2* kf = g_Kf + (size_t)ch * NFFT;

    // prefetch effective (canonical) Kf lines into L2
    {
        const int qe0 = min(tid, partner_block(tid));
        const int qe1 = min(tid + NT, partner_block(tid + NT));
        asm volatile("prefetch.global.L2 [%0];" :: "l"(kf + 16 * qe0));
        asm volatile("prefetch.global.L2 [%0];" :: "l"(kf + 16 * qe1));
    }

    const int jb = tid + (tid >> 4);

    // P1 fwd: radix-32, S=512; pack u0 + i*u1; top half zero
    {
        float2 xv[32];
        #pragma unroll
        for (int r = 0; r < 16; r++) {
            const int i = tid + (r << 9);
            xv[r] = make_float2(u0[i], u1[i]);
        }
        fft32_fwd<9, true>(xv, tid);
        #pragma unroll
        for (int r = 0; r < 32; r++) d[jb + 544 * r] = xv[r];
    }
    __syncthreads();

    const int j2 = tid & 15;
    const int b0 = (tid >> 4) * 544 + j2;

    // P2 fwd: radix-32, S=16
    {
        float2 xv[32];
        #pragma unroll
        for (int r = 0; r < 32; r++) xv[r] = d[b0 + 17 * r];
        fft32_fwd<4, false>(xv, j2);
        #pragma unroll
        for (int r = 0; r < 32; r++) d[b0 + 17 * r] = xv[r];
    }
    __syncthreads();

    // P3: const-twiddle fwd16 -> * Kf (Hermitian-half) -> const-twiddle inv16
    #pragma unroll
    for (int k = 0; k < 2; k++) {
        const int q  = tid + k * NT;
        const int pb = 17 * q;
        const int qb = partner_block(q);
        const bool canon = (q <= qb);
        const int qe = canon ? q : qb;
        float4 kreg[8];
        const float4* kf4 = reinterpret_cast<const float4*>(kf + 16 * qe);
        #pragma unroll
        for (int i = 0; i < 8; i++) kreg[i] = kf4[i];    // prefetch over fwd16
        float2 xv[16];
        #pragma unroll
        for (int r = 0; r < 16; r++) xv[r] = d[pb + r];
        fft16c_fwd(xv);
        if (canon) {
            #pragma unroll
            for (int i = 0; i < 8; i++) {
                xv[2*i]   = cmul(xv[2*i],   make_float2(kreg[i].x, kreg[i].y));
                xv[2*i+1] = cmul(xv[2*i+1], make_float2(kreg[i].z, kreg[i].w));
            }
        } else {
            // needed[m3] = conj(stored[15 - m3]):
            //   m3=2i   -> conj(kreg[7-i].zw)
            //   m3=2i+1 -> conj(kreg[7-i].xy)
            #pragma unroll
            for (int i = 0; i < 8; i++) {
                xv[2*i]   = cmul(xv[2*i],   make_float2(kreg[7-i].z, -kreg[7-i].w));
                xv[2*i+1] = cmul(xv[2*i+1], make_float2(kreg[7-i].x, -kreg[7-i].y));
            }
        }
        fft16c_inv(xv);
        #pragma unroll
        for (int r = 0; r < 16; r++) d[pb + r] = xv[r];
    }
    __syncthreads();

    // P2' inv
    {
        float2 xv[32];
        #pragma unroll
        for (int r = 0; r < 32; r++) xv[r] = d[b0 + 17 * r];
        fft32_inv<4, false>(xv, j2);
        #pragma unroll
        for (int r = 0; r < 32; r++) d[b0 + 17 * r] = xv[r];
    }
    __syncthreads();

    // P1' inv: half output, direct global store
    float* o0 = out + ((size_t)(2*p)     * DM + ch) * LSEQ;
    float* o1 = out + ((size_t)(2*p + 1) * DM + ch) * LSEQ;
    {
        float2 xv[32];
        #pragma unroll
        for (int r = 0; r < 32; r++) xv[r] = d[jb + 544 * r];
        fft32_inv<9, true>(xv, tid);
        #pragma unroll
        for (int r = 0; r < 16; r++) {
            const int i = tid + (r << 9);
            o0[i] = xv[r].x;
            o1[i] = xv[r].y;
        }
    }
}

// ---------------- launch ----------------------------------------------------
// Input order (metadata): x, z, t, freq, W1, b1, W2, b2, W3, b3, Wout, deltas, D
extern "C" void kernel_launch(void* const* d_in, const int* in_sizes, int n_in,
                              void* d_out, int out_size) {
    (void)in_sizes; (void)n_in; (void)out_size;
    const float* x      = (const float*)d_in[0];
    const float* z      = (const float*)d_in[1];
    const float* t      = (const float*)d_in[2];
    const float* freq   = (const float*)d_in[3];
    const float* W1     = (const float*)d_in[4];
    const float* b1     = (const float*)d_in[5];
    const float* W2     = (const float*)d_in[6];
    const float* b2     = (const float*)d_in[7];
    const float* W3     = (const float*)d_in[8];
    const float* b3     = (const float*)d_in[9];
    const float* Wout   = (const float*)d_in[10];
    const float* deltas = (const float*)d_in[11];
    const float* Dbias  = (const float*)d_in[12];
    float* out = (float*)d_out;

    cudaFuncSetAttribute(kf_kernel,   cudaFuncAttributeMaxDynamicSharedMemorySize, SMEM_BYTES);
    cudaFuncSetAttribute(conv_kernel, cudaFuncAttributeMaxDynamicSharedMemorySize, SMEM_BYTES);

    mlp_kernel<<<LSEQ / 4, 256>>>(z, freq, W1, b1, W2, b2, W3, b3);
    filt_kernel<<<dim3(LSEQ / 32, DM / 128), 256>>>(Wout, t, deltas);
    kf_kernel<<<DM / 2, NT, SMEM_BYTES>>>(Dbias);
    conv_kernel<<<dim3(2, DM), NT, SMEM_BYTES>>>(x, out);
}